// round 1
// baseline (speedup 1.0000x reference)
#include <cuda_runtime.h>
#include <math.h>

// Problem sizes (fixed by the reference)
#define BATCH 8
#define SEQ   2048
#define DIM   1024
#define BS    (BATCH * SEQ)          // 16384

// Scratch (allocation-free rule: __device__ globals)
__device__ float g_x[BS * DIM];          // 64 MB   x = x_batch @ lin_w^T + b
__device__ float g_q[BS * DIM];          // 64 MB   Q
__device__ float g_s[BATCH * SEQ * SEQ]; // 128 MB  attention scores / probs

// ---------------------------------------------------------------------------
// Tiled SGEMM: C[M,N] = A[M,K] * op(B) (+ bias)
//   TRANSB=false: B is [K,N] row-major (NN)
//   TRANSB=true : B is [N,K] row-major (NT)
//   CAUSAL_SKIP_UPPER: skip tile-blocks strictly above the diagonal (scores)
//   CAUSAL_KLIMIT    : limit K-loop to (by+1)*BM (P·V, probs are 0 beyond)
// 128x128 tile, BK=16, 256 threads, 8x8 per-thread micro tile.
// All dims here are multiples of the tile sizes (no edge handling needed).
// ---------------------------------------------------------------------------
#define BM 128
#define BN 128
#define BKK 16
#define TM 8
#define TN 8

template<bool TRANSB, bool BIAS, bool CAUSAL_SKIP_UPPER, bool CAUSAL_KLIMIT>
__global__ __launch_bounds__(256)
void sgemm_kernel(const float* __restrict__ Aall, const float* __restrict__ Ball,
                  const float* __restrict__ bias, float* __restrict__ Call,
                  int M, int N, int K,
                  long long strideA, long long strideB, long long strideC)
{
    const int bx = blockIdx.x, by = blockIdx.y, bz = blockIdx.z;
    if (CAUSAL_SKIP_UPPER && bx > by) return;

    const float* A = Aall + (long long)bz * strideA;
    const float* B = Ball + (long long)bz * strideB;
    float*       C = Call + (long long)bz * strideC;

    int Keff = K;
    if (CAUSAL_KLIMIT) {
        int lim = (by + 1) * BM;
        Keff = lim < K ? lim : K;
    }

    __shared__ float As[BKK][BM];
    __shared__ float Bs[BKK][BN];

    const int tid = threadIdx.x;
    const int tx  = tid & 15;   // 0..15 (col group)
    const int ty  = tid >> 4;   // 0..15 (row group)

    const int row0 = by * BM;
    const int col0 = bx * BN;

    float acc[TM][TN];
    #pragma unroll
    for (int i = 0; i < TM; i++)
        #pragma unroll
        for (int j = 0; j < TN; j++) acc[i][j] = 0.0f;

    for (int k0 = 0; k0 < Keff; k0 += BKK) {
        // ---- load A tile (BM x BK), transpose into As[k][m] ----
        #pragma unroll
        for (int l = 0; l < 2; l++) {
            int f  = tid + l * 256;       // 0..511 float4 slots
            int m  = f >> 2;              // row within tile
            int kf = (f & 3) << 2;        // k offset (0,4,8,12)
            float4 v = *(const float4*)&A[(long long)(row0 + m) * K + (k0 + kf)];
            As[kf + 0][m] = v.x; As[kf + 1][m] = v.y;
            As[kf + 2][m] = v.z; As[kf + 3][m] = v.w;
        }
        // ---- load B tile into Bs[k][n] ----
        if (TRANSB) {
            #pragma unroll
            for (int l = 0; l < 2; l++) {
                int f  = tid + l * 256;
                int n  = f >> 2;
                int kf = (f & 3) << 2;
                float4 v = *(const float4*)&B[(long long)(col0 + n) * K + (k0 + kf)];
                Bs[kf + 0][n] = v.x; Bs[kf + 1][n] = v.y;
                Bs[kf + 2][n] = v.z; Bs[kf + 3][n] = v.w;
            }
        } else {
            #pragma unroll
            for (int l = 0; l < 2; l++) {
                int f  = tid + l * 256;
                int kk = f >> 5;              // / (BN/4)
                int nf = (f & 31) << 2;
                float4 v = *(const float4*)&B[(long long)(k0 + kk) * N + (col0 + nf)];
                *(float4*)&Bs[kk][nf] = v;
            }
        }
        __syncthreads();

        #pragma unroll
        for (int kk = 0; kk < BKK; kk++) {
            float a[TM], b[TN];
            #pragma unroll
            for (int i = 0; i < TM; i++) a[i] = As[kk][ty * TM + i];
            #pragma unroll
            for (int j = 0; j < TN; j++) b[j] = Bs[kk][tx * TN + j];
            #pragma unroll
            for (int i = 0; i < TM; i++)
                #pragma unroll
                for (int j = 0; j < TN; j++)
                    acc[i][j] = fmaf(a[i], b[j], acc[i][j]);
        }
        __syncthreads();
    }

    // ---- epilogue ----
    #pragma unroll
    for (int i = 0; i < TM; i++) {
        int r = row0 + ty * TM + i;
        #pragma unroll
        for (int j = 0; j < TN; j += 4) {
            int c = col0 + tx * TN + j;
            float4 v;
            v.x = acc[i][j + 0]; v.y = acc[i][j + 1];
            v.z = acc[i][j + 2]; v.w = acc[i][j + 3];
            if (BIAS) {
                v.x += bias[c + 0]; v.y += bias[c + 1];
                v.z += bias[c + 2]; v.w += bias[c + 3];
            }
            *(float4*)&C[(long long)r * N + c] = v;
        }
    }
}

// ---------------------------------------------------------------------------
// Causal softmax over score rows. One block per (q, b). Row length q+1 valid;
// entries k > q are overwritten with exact zeros (enables dense P·V tiles).
// No 1/sqrt(d) scaling (per reference).
// ---------------------------------------------------------------------------
__global__ __launch_bounds__(256)
void softmax_causal_kernel(float* __restrict__ S)
{
    const int q = blockIdx.x;
    const int b = blockIdx.y;
    float* row = S + ((long long)b * SEQ + q) * SEQ;
    const int n = q + 1;
    const int tid = threadIdx.x;

    __shared__ float sh[8];

    // max
    float m = -INFINITY;
    for (int i = tid; i < n; i += 256) m = fmaxf(m, row[i]);
    #pragma unroll
    for (int o = 16; o; o >>= 1) m = fmaxf(m, __shfl_xor_sync(0xffffffffu, m, o));
    if ((tid & 31) == 0) sh[tid >> 5] = m;
    __syncthreads();
    float mr = sh[0];
    #pragma unroll
    for (int i = 1; i < 8; i++) mr = fmaxf(mr, sh[i]);
    __syncthreads();

    // exp + sum
    float s = 0.0f;
    for (int i = tid; i < n; i += 256) {
        float e = __expf(row[i] - mr);
        row[i] = e;
        s += e;
    }
    #pragma unroll
    for (int o = 16; o; o >>= 1) s += __shfl_xor_sync(0xffffffffu, s, o);
    if ((tid & 31) == 0) sh[tid >> 5] = s;
    __syncthreads();
    float sr = 0.0f;
    #pragma unroll
    for (int i = 0; i < 8; i++) sr += sh[i];
    float inv = 1.0f / sr;

    // normalize + zero-fill masked tail
    for (int i = tid; i < n; i += 256) row[i] *= inv;
    for (int i = n + tid; i < SEQ; i += 256) row[i] = 0.0f;
}

// ---------------------------------------------------------------------------
extern "C" void kernel_launch(void* const* d_in, const int* in_sizes, int n_in,
                              void* d_out, int out_size)
{
    const float* x_batch = (const float*)d_in[0];  // [8,2048,1024]
    const float* lin_w   = (const float*)d_in[1];  // [1024,1024] (out,in)
    const float* lin_b   = (const float*)d_in[2];  // [1024]
    const float* W_q     = (const float*)d_in[3];  // [1024,1024]
    const float* W_k     = (const float*)d_in[4];
    const float* W_v     = (const float*)d_in[5];

    float* outF = (float*)d_out;                         // F [8,2048,1024]
    float* outK = outF + (long long)BS * DIM;            // cache[0] = K
    float* outV = outK + (long long)BS * DIM;            // cache[1] = V

    float* xs; cudaGetSymbolAddress((void**)&xs, g_x);
    float* qs; cudaGetSymbolAddress((void**)&qs, g_q);
    float* ss; cudaGetSymbolAddress((void**)&ss, g_s);

    dim3 thr(256);

    // 1) x = x_batch @ lin_w^T + lin_b        [16384,1024]
    {
        dim3 grid(DIM / BN, BS / BM, 1);
        sgemm_kernel<true, true, false, false><<<grid, thr>>>(
            x_batch, lin_w, lin_b, xs, BS, DIM, DIM, 0, 0, 0);
    }
    // 2) Q, K, V = x @ W_{q,k,v}              [16384,1024] each
    {
        dim3 grid(DIM / BN, BS / BM, 1);
        sgemm_kernel<false, false, false, false><<<grid, thr>>>(
            xs, W_q, nullptr, qs, BS, DIM, DIM, 0, 0, 0);
        sgemm_kernel<false, false, false, false><<<grid, thr>>>(
            xs, W_k, nullptr, outK, BS, DIM, DIM, 0, 0, 0);
        sgemm_kernel<false, false, false, false><<<grid, thr>>>(
            xs, W_v, nullptr, outV, BS, DIM, DIM, 0, 0, 0);
    }
    // 3) scores = Q @ K^T (batched, causal block skip)   [8][2048,2048]
    {
        dim3 grid(SEQ / BN, SEQ / BM, BATCH);
        sgemm_kernel<true, false, true, false><<<grid, thr>>>(
            qs, outK, nullptr, ss, SEQ, SEQ, DIM,
            (long long)SEQ * DIM, (long long)SEQ * DIM, (long long)SEQ * SEQ);
    }
    // 4) causal softmax in-place on scores
    {
        dim3 grid(SEQ, BATCH);
        softmax_causal_kernel<<<grid, thr>>>(ss);
    }
    // 5) F = P @ V (batched, causal K-limit)             [8][2048,1024]
    {
        dim3 grid(DIM / BN, SEQ / BM, BATCH);
        sgemm_kernel<false, false, false, true><<<grid, thr>>>(
            ss, outV, nullptr, outF, SEQ, DIM, SEQ,
            (long long)SEQ * SEQ, (long long)SEQ * DIM, (long long)SEQ * DIM);
    }
}

// round 3
// speedup vs baseline: 1.9973x; 1.9973x over previous
#include <cuda_runtime.h>
#include <cuda_fp16.h>
#include <math.h>
#include <stdint.h>

#define BATCH 8
#define SEQ   2048
#define DIM   1024
#define BS    (BATCH * SEQ)   // 16384

// ---------------------------------------------------------------------------
// Scratch (__device__ globals: allocation-free rule)
// ---------------------------------------------------------------------------
__device__ __half g_xb_hi[BS * DIM], g_xb_lo[BS * DIM];
__device__ __half g_x_hi [BS * DIM], g_x_lo [BS * DIM];
__device__ __half g_q_hi [BS * DIM], g_q_lo [BS * DIM];
__device__ __half g_k_hi [BS * DIM], g_k_lo [BS * DIM];
__device__ __half g_vt_hi[BATCH * DIM * SEQ], g_vt_lo[BATCH * DIM * SEQ];
__device__ __half g_p_hi [BATCH * SEQ * SEQ], g_p_lo [BATCH * SEQ * SEQ];
__device__ __half g_lw_hi[DIM * DIM], g_lw_lo[DIM * DIM];
__device__ __half g_wq_hi[DIM * DIM], g_wq_lo[DIM * DIM];
__device__ __half g_wk_hi[DIM * DIM], g_wk_lo[DIM * DIM];
__device__ __half g_wv_hi[DIM * DIM], g_wv_lo[DIM * DIM];
__device__ float  g_s[BATCH * SEQ * SEQ];

// ---------------------------------------------------------------------------
// helpers
// ---------------------------------------------------------------------------
__device__ __forceinline__ uint32_t smem_u32(const void* p) {
    uint32_t a;
    asm("{ .reg .u64 t; cvta.to.shared.u64 t, %1; cvt.u32.u64 %0, t; }"
        : "=r"(a) : "l"(p));
    return a;
}

__device__ __forceinline__ void cp16(uint32_t saddr, const void* gaddr) {
    asm volatile("cp.async.cg.shared.global [%0], [%1], 16;" :: "r"(saddr), "l"(gaddr));
}
__device__ __forceinline__ void cp_commit() {
    asm volatile("cp.async.commit_group;" ::: "memory");
}
__device__ __forceinline__ void cp_wait(int n) {
    if (n <= 0)      asm volatile("cp.async.wait_group 0;" ::: "memory");
    else if (n == 1) asm volatile("cp.async.wait_group 1;" ::: "memory");
    else             asm volatile("cp.async.wait_group 2;" ::: "memory");
}

__device__ __forceinline__ void ldsm4(uint32_t (&r)[4], uint32_t addr) {
    asm volatile("ldmatrix.sync.aligned.m8n8.x4.shared.b16 {%0,%1,%2,%3}, [%4];"
        : "=r"(r[0]), "=r"(r[1]), "=r"(r[2]), "=r"(r[3]) : "r"(addr));
}

__device__ __forceinline__ void mma_f16(float* c, const uint32_t* a, const uint32_t* b) {
    asm volatile("mma.sync.aligned.m16n8k16.row.col.f32.f16.f16.f32 "
        "{%0,%1,%2,%3}, {%4,%5,%6,%7}, {%8,%9}, {%0,%1,%2,%3};"
        : "+f"(c[0]), "+f"(c[1]), "+f"(c[2]), "+f"(c[3])
        : "r"(a[0]), "r"(a[1]), "r"(a[2]), "r"(a[3]), "r"(b[0]), "r"(b[1]));
}

// XOR swizzle for 128B rows of 16B sectors (conflict-free ldmatrix + cp.async)
__device__ __forceinline__ uint32_t sw(uint32_t off) {
    return off ^ ((off >> 3) & 0x70);
}

__device__ __forceinline__ void split1(float v, __half& h, __half& l) {
    h = __float2half(v);
    l = __float2half(v - __half2float(h));
}

// ---------------------------------------------------------------------------
// split-fp16 GEMM on HMMA: C[M,N](fp32) = (Ahi+Alo)[M,K] * (Bhi+Blo)[N,K]^T
//   terms: Ah*Bh + Al*Bh + Ah*Bl   (3x mma)
// 128x128 CTA tile, BK=64, 3-stage cp.async, 256 threads (8 warps of 64x32).
// EPI: 0 = fp32 out, 1 = fp16 hi/lo split out, 2 = both
// ---------------------------------------------------------------------------
#define NSTG 3
#define TILE_BYTES  16384                 // 128 rows x 128B (64 halves)
#define STAGE_BYTES (4 * TILE_BYTES)      // Ahi, Alo, Bhi, Blo
#define SMEM_DYN    (NSTG * STAGE_BYTES + 1024)

// load one 128x64 fp16 tile, swizzled (4 cp.async per thread at 256 thr)
__device__ __forceinline__ void load_tile(const __half* __restrict__ g,
                                          int row0, int k0, int ld,
                                          uint32_t sdst, int tid) {
    #pragma unroll
    for (int i = 0; i < 4; i++) {
        int gr = i * 256 + tid;          // 0..1023
        int r  = gr >> 3;                // tile row
        int sec = gr & 7;                // 16B sector
        cp16(sdst + sw((uint32_t)(r * 128 + sec * 16)),
             (const void*)(g + (long long)(row0 + r) * ld + (k0 + sec * 8)));
    }
}

template<int EPI, bool BIAS, bool CAUSAL, bool KLIM>
__global__ void __launch_bounds__(256)
gemm_mma(const __half* __restrict__ Ahi, const __half* __restrict__ Alo,
         const __half* __restrict__ Bhi, const __half* __restrict__ Blo,
         const float* __restrict__ bias,
         float* __restrict__ Cf, __half* __restrict__ Chi, __half* __restrict__ Clo,
         int K, int ldC,
         long long aB, long long bB, long long cB)
{
    const int bx = blockIdx.x, by = blockIdx.y, z = blockIdx.z;
    if (CAUSAL && bx > by) return;

    extern __shared__ char smem[];
    const uint32_t stage0 = (smem_u32(smem) + 1023u) & ~1023u;

    const int tid  = threadIdx.x;
    const int lane = tid & 31;
    const int wid  = tid >> 5;
    const int wm   = (wid & 1) * 64;     // warp m offset in tile
    const int wn   = (wid >> 1) * 32;    // warp n offset in tile

    const __half* A_hi = Ahi + (long long)z * aB;
    const __half* A_lo = Alo + (long long)z * aB;
    const __half* B_hi = Bhi + (long long)z * bB;
    const __half* B_lo = Blo + (long long)z * bB;

    int nk = K >> 6;
    if (KLIM) { int lim = 2 * (by + 1); if (lim < nk) nk = lim; }
    const int row0 = by * 128;
    const int col0 = bx * 128;

    float acc[4][4][4];
    #pragma unroll
    for (int i = 0; i < 4; i++)
        #pragma unroll
        for (int j = 0; j < 4; j++)
            #pragma unroll
            for (int c = 0; c < 4; c++) acc[i][j][c] = 0.0f;

    // per-lane ldmatrix address components
    const int a_r = ((lane >> 3) & 1) * 8 + (lane & 7);  // + mi*16 + wm
    const int a_c = (lane >> 4) * 16;                     // + ks*32
    const int b_r = ((lane >> 4) & 1) * 8 + (lane & 7);   // + pair*16 + wn
    const int b_c = ((lane >> 3) & 1) * 16;               // + ks*32

    // prologue
    const int npre = (NSTG - 1 < nk) ? NSTG - 1 : nk;
    for (int c = 0; c < npre; c++) {
        uint32_t st = stage0 + c * STAGE_BYTES;
        load_tile(A_hi, row0, c * 64, K, st + 0 * TILE_BYTES, tid);
        load_tile(A_lo, row0, c * 64, K, st + 1 * TILE_BYTES, tid);
        load_tile(B_hi, col0, c * 64, K, st + 2 * TILE_BYTES, tid);
        load_tile(B_lo, col0, c * 64, K, st + 3 * TILE_BYTES, tid);
        cp_commit();
    }

    for (int k = 0; k < nk; k++) {
        const int s = k % NSTG;
        const int cl = k + NSTG - 1;
        if (cl < nk) {
            uint32_t st = stage0 + (cl % NSTG) * STAGE_BYTES;
            load_tile(A_hi, row0, cl * 64, K, st + 0 * TILE_BYTES, tid);
            load_tile(A_lo, row0, cl * 64, K, st + 1 * TILE_BYTES, tid);
            load_tile(B_hi, col0, cl * 64, K, st + 2 * TILE_BYTES, tid);
            load_tile(B_lo, col0, cl * 64, K, st + 3 * TILE_BYTES, tid);
            cp_commit();
        }
        int inloop = (nk > NSTG - 1) ? min(k + 1, nk - (NSTG - 1)) : 0;
        cp_wait(npre + inloop - (k + 1));
        __syncthreads();

        const uint32_t sAh = stage0 + s * STAGE_BYTES + 0 * TILE_BYTES;
        const uint32_t sAl = sAh + TILE_BYTES;
        const uint32_t sBh = sAh + 2 * TILE_BYTES;
        const uint32_t sBl = sAh + 3 * TILE_BYTES;

        #pragma unroll
        for (int ks = 0; ks < 4; ks++) {
            uint32_t ah[4][4], al[4][4], bh[2][4], bl[2][4];
            #pragma unroll
            for (int mi = 0; mi < 4; mi++) {
                uint32_t off = sw((uint32_t)((wm + mi * 16 + a_r) * 128 + ks * 32 + a_c));
                ldsm4(ah[mi], sAh + off);
                ldsm4(al[mi], sAl + off);
            }
            #pragma unroll
            for (int p = 0; p < 2; p++) {
                uint32_t off = sw((uint32_t)((wn + p * 16 + b_r) * 128 + ks * 32 + b_c));
                ldsm4(bh[p], sBh + off);
                ldsm4(bl[p], sBl + off);
            }
            #pragma unroll
            for (int mi = 0; mi < 4; mi++)
                #pragma unroll
                for (int nj = 0; nj < 4; nj++) {
                    const uint32_t* bph = &bh[nj >> 1][(nj & 1) * 2];
                    const uint32_t* bpl = &bl[nj >> 1][(nj & 1) * 2];
                    mma_f16(acc[mi][nj], ah[mi], bph);   // Ah*Bh
                    mma_f16(acc[mi][nj], al[mi], bph);   // Al*Bh
                    mma_f16(acc[mi][nj], ah[mi], bpl);   // Ah*Bl
                }
        }
        __syncthreads();
    }

    // ---- epilogue ----
    #pragma unroll
    for (int mi = 0; mi < 4; mi++) {
        const int r0 = row0 + wm + mi * 16 + (lane >> 2);
        #pragma unroll
        for (int nj = 0; nj < 4; nj++) {
            const int c = col0 + wn + nj * 8 + (lane & 3) * 2;
            float v0 = acc[mi][nj][0], v1 = acc[mi][nj][1];
            float v2 = acc[mi][nj][2], v3 = acc[mi][nj][3];
            if (BIAS) {
                float b0 = bias[c], b1 = bias[c + 1];
                v0 += b0; v1 += b1; v2 += b0; v3 += b1;
            }
            if (EPI == 0 || EPI == 2) {
                float* cp = Cf + (long long)z * cB + (long long)r0 * ldC + c;
                *(float2*)cp = make_float2(v0, v1);
                *(float2*)(cp + 8LL * ldC) = make_float2(v2, v3);
            }
            if (EPI >= 1) {
                __half h0, l0, h1, l1;
                split1(v0, h0, l0); split1(v1, h1, l1);
                __half* hp = Chi + (long long)z * cB + (long long)r0 * ldC + c;
                __half* lp = Clo + (long long)z * cB + (long long)r0 * ldC + c;
                *(__half2*)hp = __halves2half2(h0, h1);
                *(__half2*)lp = __halves2half2(l0, l1);
                split1(v2, h0, l0); split1(v3, h1, l1);
                *(__half2*)(hp + 8LL * ldC) = __halves2half2(h0, h1);
                *(__half2*)(lp + 8LL * ldC) = __halves2half2(l0, l1);
            }
        }
    }
}

// ---------------------------------------------------------------------------
// elementwise fp32 -> fp16 hi/lo split
// ---------------------------------------------------------------------------
__global__ void split_kernel(const float* __restrict__ in,
                             __half* __restrict__ hi,
                             __half* __restrict__ lo, int n4)
{
    int i = blockIdx.x * blockDim.x + threadIdx.x;
    if (i >= n4) return;
    float4 v = ((const float4*)in)[i];
    __half h0, l0, h1, l1, h2, l2, h3, l3;
    split1(v.x, h0, l0); split1(v.y, h1, l1);
    split1(v.z, h2, l2); split1(v.w, h3, l3);
    __half2 ha = __halves2half2(h0, h1), hb = __halves2half2(h2, h3);
    __half2 la = __halves2half2(l0, l1), lb = __halves2half2(l2, l3);
    ((uint2*)hi)[i] = make_uint2(*(uint32_t*)&ha, *(uint32_t*)&hb);
    ((uint2*)lo)[i] = make_uint2(*(uint32_t*)&la, *(uint32_t*)&lb);
}

// transpose + split: fp32 [Z][R][C] -> fp16 hi/lo [Z][C][R]
__global__ void tsplit_kernel(const float* __restrict__ in,
                              __half* __restrict__ hi,
                              __half* __restrict__ lo, int R, int C)
{
    __shared__ float t[32][33];
    const long long zoff = (long long)blockIdx.z * R * C;
    const int c0 = blockIdx.x * 32, r0 = blockIdx.y * 32;
    const int tx = threadIdx.x, ty = threadIdx.y;
    #pragma unroll
    for (int i = 0; i < 4; i++)
        t[ty + 8 * i][tx] = in[zoff + (long long)(r0 + ty + 8 * i) * C + c0 + tx];
    __syncthreads();
    #pragma unroll
    for (int i = 0; i < 4; i++) {
        float v = t[tx][ty + 8 * i];
        __half h, l; split1(v, h, l);
        long long o = zoff + (long long)(c0 + ty + 8 * i) * R + r0 + tx;
        hi[o] = h; lo[o] = l;
    }
}

// ---------------------------------------------------------------------------
// causal softmax fp32 scores -> fp16 hi/lo probs, zero-fill to end of the
// 128-block containing the diagonal (PV GEMM never reads beyond it).
// ---------------------------------------------------------------------------
__global__ __launch_bounds__(256)
void softmax_causal_kernel(const float* __restrict__ S,
                           __half* __restrict__ Phi,
                           __half* __restrict__ Plo)
{
    const int q = blockIdx.x, b = blockIdx.y;
    const long long off = ((long long)b * SEQ + q) * SEQ;
    const float* row = S + off;
    const int n = q + 1;
    const int tid = threadIdx.x;
    __shared__ float sh[8];

    float m = -INFINITY;
    for (int i = tid; i < n; i += 256) m = fmaxf(m, row[i]);
    #pragma unroll
    for (int o = 16; o; o >>= 1) m = fmaxf(m, __shfl_xor_sync(0xffffffffu, m, o));
    if ((tid & 31) == 0) sh[tid >> 5] = m;
    __syncthreads();
    float mr = sh[0];
    #pragma unroll
    for (int i = 1; i < 8; i++) mr = fmaxf(mr, sh[i]);
    __syncthreads();

    float s = 0.0f;
    for (int i = tid; i < n; i += 256) s += __expf(row[i] - mr);
    #pragma unroll
    for (int o = 16; o; o >>= 1) s += __shfl_xor_sync(0xffffffffu, s, o);
    if ((tid & 31) == 0) sh[tid >> 5] = s;
    __syncthreads();
    float sr = 0.0f;
    #pragma unroll
    for (int i = 0; i < 8; i++) sr += sh[i];
    const float inv = 1.0f / sr;

    for (int i = tid; i < n; i += 256) {
        float p = __expf(row[i] - mr) * inv;
        __half h, l; split1(p, h, l);
        Phi[off + i] = h; Plo[off + i] = l;
    }
    const int fend = ((q >> 7) + 1) << 7;   // end of diagonal 128-block
    const __half z16 = __float2half(0.0f);
    for (int i = n + tid; i < fend; i += 256) {
        Phi[off + i] = z16; Plo[off + i] = z16;
    }
}

// ---------------------------------------------------------------------------
extern "C" void kernel_launch(void* const* d_in, const int* in_sizes, int n_in,
                              void* d_out, int out_size)
{
    const float* x_batch = (const float*)d_in[0];
    const float* lin_w   = (const float*)d_in[1];
    const float* lin_b   = (const float*)d_in[2];
    const float* W_q     = (const float*)d_in[3];
    const float* W_k     = (const float*)d_in[4];
    const float* W_v     = (const float*)d_in[5];

    float* outF = (float*)d_out;
    float* outK = outF + (long long)BS * DIM;
    float* outV = outK + (long long)BS * DIM;

    __half *xb_hi, *xb_lo, *x_hi, *x_lo, *q_hi, *q_lo, *k_hi, *k_lo;
    __half *vt_hi, *vt_lo, *p_hi, *p_lo;
    __half *lw_hi, *lw_lo, *wq_hi, *wq_lo, *wk_hi, *wk_lo, *wv_hi, *wv_lo;
    float* ss;
    cudaGetSymbolAddress((void**)&xb_hi, g_xb_hi); cudaGetSymbolAddress((void**)&xb_lo, g_xb_lo);
    cudaGetSymbolAddress((void**)&x_hi,  g_x_hi);  cudaGetSymbolAddress((void**)&x_lo,  g_x_lo);
    cudaGetSymbolAddress((void**)&q_hi,  g_q_hi);  cudaGetSymbolAddress((void**)&q_lo,  g_q_lo);
    cudaGetSymbolAddress((void**)&k_hi,  g_k_hi);  cudaGetSymbolAddress((void**)&k_lo,  g_k_lo);
    cudaGetSymbolAddress((void**)&vt_hi, g_vt_hi); cudaGetSymbolAddress((void**)&vt_lo, g_vt_lo);
    cudaGetSymbolAddress((void**)&p_hi,  g_p_hi);  cudaGetSymbolAddress((void**)&p_lo,  g_p_lo);
    cudaGetSymbolAddress((void**)&lw_hi, g_lw_hi); cudaGetSymbolAddress((void**)&lw_lo, g_lw_lo);
    cudaGetSymbolAddress((void**)&wq_hi, g_wq_hi); cudaGetSymbolAddress((void**)&wq_lo, g_wq_lo);
    cudaGetSymbolAddress((void**)&wk_hi, g_wk_hi); cudaGetSymbolAddress((void**)&wk_lo, g_wk_lo);
    cudaGetSymbolAddress((void**)&wv_hi, g_wv_hi); cudaGetSymbolAddress((void**)&wv_lo, g_wv_lo);
    cudaGetSymbolAddress((void**)&ss, g_s);

    cudaFuncSetAttribute(gemm_mma<1, true,  false, false>, cudaFuncAttributeMaxDynamicSharedMemorySize, SMEM_DYN);
    cudaFuncSetAttribute(gemm_mma<1, false, false, false>, cudaFuncAttributeMaxDynamicSharedMemorySize, SMEM_DYN);
    cudaFuncSetAttribute(gemm_mma<2, false, false, false>, cudaFuncAttributeMaxDynamicSharedMemorySize, SMEM_DYN);
    cudaFuncSetAttribute(gemm_mma<0, false, false, false>, cudaFuncAttributeMaxDynamicSharedMemorySize, SMEM_DYN);
    cudaFuncSetAttribute(gemm_mma<0, false, true,  false>, cudaFuncAttributeMaxDynamicSharedMemorySize, SMEM_DYN);
    cudaFuncSetAttribute(gemm_mma<0, false, false, true >, cudaFuncAttributeMaxDynamicSharedMemorySize, SMEM_DYN);

    // ---- input splits ----
    split_kernel<<<(BS * DIM / 4 + 255) / 256, 256>>>(x_batch, xb_hi, xb_lo, BS * DIM / 4);
    split_kernel<<<(DIM * DIM / 4 + 255) / 256, 256>>>(lin_w, lw_hi, lw_lo, DIM * DIM / 4);
    {
        dim3 g(DIM / 32, DIM / 32, 1), t(32, 8);
        tsplit_kernel<<<g, t>>>(W_q, wq_hi, wq_lo, DIM, DIM);
        tsplit_kernel<<<g, t>>>(W_k, wk_hi, wk_lo, DIM, DIM);
        tsplit_kernel<<<g, t>>>(W_v, wv_hi, wv_lo, DIM, DIM);
    }

    // ---- G1: x = x_batch @ lin_w^T + b  -> fp16 split ----
    {
        dim3 g(DIM / 128, BS / 128, 1);
        gemm_mma<1, true, false, false><<<g, 256, SMEM_DYN>>>(
            xb_hi, xb_lo, lw_hi, lw_lo, lin_b,
            nullptr, x_hi, x_lo, DIM, DIM, 0, 0, 0);
    }
    // ---- G2/3/4: Q (split), K (f32 cache + split), V (f32 cache) ----
    {
        dim3 g(DIM / 128, BS / 128, 1);
        gemm_mma<1, false, false, false><<<g, 256, SMEM_DYN>>>(
            x_hi, x_lo, wq_hi, wq_lo, nullptr,
            nullptr, q_hi, q_lo, DIM, DIM, 0, 0, 0);
        gemm_mma<2, false, false, false><<<g, 256, SMEM_DYN>>>(
            x_hi, x_lo, wk_hi, wk_lo, nullptr,
            outK, k_hi, k_lo, DIM, DIM, 0, 0, 0);
        gemm_mma<0, false, false, false><<<g, 256, SMEM_DYN>>>(
            x_hi, x_lo, wv_hi, wv_lo, nullptr,
            outV, nullptr, nullptr, DIM, DIM, 0, 0, 0);
    }
    // ---- V transpose+split: [8][2048][1024] -> [8][1024][2048] ----
    {
        dim3 g(DIM / 32, SEQ / 32, BATCH), t(32, 8);
        tsplit_kernel<<<g, t>>>(outV, vt_hi, vt_lo, SEQ, DIM);
    }
    // ---- G5: scores = Q @ K^T (batched, causal block skip) ----
    {
        dim3 g(SEQ / 128, SEQ / 128, BATCH);
        gemm_mma<0, false, true, false><<<g, 256, SMEM_DYN>>>(
            q_hi, q_lo, k_hi, k_lo, nullptr,
            ss, nullptr, nullptr, DIM, SEQ,
            (long long)SEQ * DIM, (long long)SEQ * DIM, (long long)SEQ * SEQ);
    }
    // ---- softmax -> fp16 split probs ----
    {
        dim3 g(SEQ, BATCH);
        softmax_causal_kernel<<<g, 256>>>(ss, p_hi, p_lo);
    }
    // ---- G6: F = P @ V^T-layout (batched, causal K-limit) ----
    {
        dim3 g(DIM / 128, SEQ / 128, BATCH);
        gemm_mma<0, false, false, true><<<g, 256, SMEM_DYN>>>(
            p_hi, p_lo, vt_hi, vt_lo, nullptr,
            outF, nullptr, nullptr, SEQ, DIM,
            (long long)SEQ * SEQ, (long long)DIM * SEQ, (long long)SEQ * DIM);
    }
}

// round 4
// speedup vs baseline: 3.0067x; 1.5054x over previous
#include <cuda_runtime.h>
#include <cuda_fp16.h>
#include <math.h>
#include <stdint.h>

#define BATCH 8
#define SEQ   2048
#define DIM   1024
#define BS    (BATCH * SEQ)   // 16384

// ---------------------------------------------------------------------------
// Scratch (__device__ globals: allocation-free rule)
// ---------------------------------------------------------------------------
__device__ __half g_xb_hi[BS * DIM], g_xb_lo[BS * DIM];
__device__ __half g_x_hi [BS * DIM], g_x_lo [BS * DIM];
__device__ __half g_q_hi [BS * DIM], g_q_lo [BS * DIM];
__device__ __half g_k_hi [BS * DIM], g_k_lo [BS * DIM];
__device__ __half g_vt_hi[BATCH * DIM * SEQ], g_vt_lo[BATCH * DIM * SEQ];
__device__ __half g_p_hi [BATCH * SEQ * SEQ], g_p_lo [BATCH * SEQ * SEQ];
__device__ __half g_lw_hi[DIM * DIM], g_lw_lo[DIM * DIM];
__device__ __half g_wq_hi[DIM * DIM], g_wq_lo[DIM * DIM];
__device__ __half g_wk_hi[DIM * DIM], g_wk_lo[DIM * DIM];
__device__ __half g_wv_hi[DIM * DIM], g_wv_lo[DIM * DIM];
__device__ float  g_s[BATCH * SEQ * SEQ];

// ---------------------------------------------------------------------------
// helpers
// ---------------------------------------------------------------------------
__device__ __forceinline__ uint32_t smem_u32(const void* p) {
    uint32_t a;
    asm("{ .reg .u64 t; cvta.to.shared.u64 t, %1; cvt.u32.u64 %0, t; }"
        : "=r"(a) : "l"(p));
    return a;
}

__device__ __forceinline__ void cp16(uint32_t saddr, const void* gaddr) {
    asm volatile("cp.async.cg.shared.global [%0], [%1], 16;" :: "r"(saddr), "l"(gaddr));
}
__device__ __forceinline__ void cp_commit() {
    asm volatile("cp.async.commit_group;" ::: "memory");
}
__device__ __forceinline__ void cp_wait(int n) {
    if (n <= 0)      asm volatile("cp.async.wait_group 0;" ::: "memory");
    else if (n == 1) asm volatile("cp.async.wait_group 1;" ::: "memory");
    else             asm volatile("cp.async.wait_group 2;" ::: "memory");
}

__device__ __forceinline__ void ldsm4(uint32_t (&r)[4], uint32_t addr) {
    asm volatile("ldmatrix.sync.aligned.m8n8.x4.shared.b16 {%0,%1,%2,%3}, [%4];"
        : "=r"(r[0]), "=r"(r[1]), "=r"(r[2]), "=r"(r[3]) : "r"(addr));
}

__device__ __forceinline__ void mma_f16(float* c, const uint32_t* a, const uint32_t* b) {
    asm volatile("mma.sync.aligned.m16n8k16.row.col.f32.f16.f16.f32 "
        "{%0,%1,%2,%3}, {%4,%5,%6,%7}, {%8,%9}, {%0,%1,%2,%3};"
        : "+f"(c[0]), "+f"(c[1]), "+f"(c[2]), "+f"(c[3])
        : "r"(a[0]), "r"(a[1]), "r"(a[2]), "r"(a[3]), "r"(b[0]), "r"(b[1]));
}

// SW64 swizzle for 64B rows: sector ^= (row>>1)&3  — conflict-free ldmatrix
__device__ __forceinline__ uint32_t sw64(uint32_t off) {
    return off ^ ((off >> 3) & 0x30);
}

__device__ __forceinline__ void split1(float v, __half& h, __half& l) {
    h = __float2half(v);
    l = __float2half(v - __half2float(h));
}

// ---------------------------------------------------------------------------
// split-fp16 GEMM on HMMA: C[M,N](fp32) = (Ahi+Alo)[M,K] * (Bhi+Blo)[N,K]^T
//   terms: Ah*Bh + Al*Bh + Ah*Bl
// 128x128 CTA tile, BK=32, 3-stage cp.async, 256 threads, 2 CTAs/SM (96KB).
// EPI: 0 = fp32 out, 1 = fp16 hi/lo split out, 2 = both
// ---------------------------------------------------------------------------
#define NSTG 3
#define TILE_BYTES  8192                  // 128 rows x 64B (32 halves)
#define STAGE_BYTES (4 * TILE_BYTES)      // Ahi, Alo, Bhi, Blo  = 32KB
#define SMEM_DYN    (NSTG * STAGE_BYTES + 1024)   // 99328

// load one 128x32 fp16 tile, SW64-swizzled (2 cp.async per thread)
__device__ __forceinline__ void load_tile(const __half* __restrict__ g,
                                          int row0, int k0, int ld,
                                          uint32_t sdst, int tid) {
    #pragma unroll
    for (int i = 0; i < 2; i++) {
        int gr = i * 256 + tid;          // 0..511
        int r  = gr >> 2;                // tile row 0..127
        int sec = gr & 3;                // 16B sector 0..3
        cp16(sdst + sw64((uint32_t)(r * 64 + sec * 16)),
             (const void*)(g + (long long)(row0 + r) * ld + (k0 + sec * 8)));
    }
}

template<int EPI, bool BIAS, bool CAUSAL, bool KLIM>
__global__ void __launch_bounds__(256, 2)
gemm_mma(const __half* __restrict__ Ahi, const __half* __restrict__ Alo,
         const __half* __restrict__ Bhi, const __half* __restrict__ Blo,
         const float* __restrict__ bias,
         float* __restrict__ Cf, __half* __restrict__ Chi, __half* __restrict__ Clo,
         int K, int ldC,
         long long aB, long long bB, long long cB)
{
    const int bx = blockIdx.x, by = blockIdx.y, z = blockIdx.z;
    if (CAUSAL && bx > by) return;

    extern __shared__ char smem[];
    const uint32_t stage0 = (smem_u32(smem) + 1023u) & ~1023u;

    const int tid  = threadIdx.x;
    const int lane = tid & 31;
    const int wid  = tid >> 5;
    const int wm   = (wid & 1) * 64;     // warp m offset in tile
    const int wn   = (wid >> 1) * 32;    // warp n offset in tile

    const __half* A_hi = Ahi + (long long)z * aB;
    const __half* A_lo = Alo + (long long)z * aB;
    const __half* B_hi = Bhi + (long long)z * bB;
    const __half* B_lo = Blo + (long long)z * bB;

    int nk = K >> 5;
    if (KLIM) { int lim = 4 * (by + 1); if (lim < nk) nk = lim; }
    const int row0 = by * 128;
    const int col0 = bx * 128;

    float acc[4][4][4];
    #pragma unroll
    for (int i = 0; i < 4; i++)
        #pragma unroll
        for (int j = 0; j < 4; j++)
            #pragma unroll
            for (int c = 0; c < 4; c++) acc[i][j][c] = 0.0f;

    // per-lane ldmatrix address components
    const int a_r = ((lane >> 3) & 1) * 8 + (lane & 7);   // + mi*16 + wm
    const int a_c = (lane >> 4) * 16;                      // + ks*32
    const int b_r = ((lane >> 4) & 1) * 8 + (lane & 7);    // + pair*16 + wn
    const int b_c = ((lane >> 3) & 1) * 16;                // + ks*32

    // prologue
    const int npre = (NSTG - 1 < nk) ? NSTG - 1 : nk;
    for (int c = 0; c < npre; c++) {
        uint32_t st = stage0 + c * STAGE_BYTES;
        load_tile(A_hi, row0, c * 32, K, st + 0 * TILE_BYTES, tid);
        load_tile(A_lo, row0, c * 32, K, st + 1 * TILE_BYTES, tid);
        load_tile(B_hi, col0, c * 32, K, st + 2 * TILE_BYTES, tid);
        load_tile(B_lo, col0, c * 32, K, st + 3 * TILE_BYTES, tid);
        cp_commit();
    }

    for (int k = 0; k < nk; k++) {
        const int s = k % NSTG;
        const int cl = k + NSTG - 1;
        if (cl < nk) {
            uint32_t st = stage0 + (cl % NSTG) * STAGE_BYTES;
            load_tile(A_hi, row0, cl * 32, K, st + 0 * TILE_BYTES, tid);
            load_tile(A_lo, row0, cl * 32, K, st + 1 * TILE_BYTES, tid);
            load_tile(B_hi, col0, cl * 32, K, st + 2 * TILE_BYTES, tid);
            load_tile(B_lo, col0, cl * 32, K, st + 3 * TILE_BYTES, tid);
            cp_commit();
        }
        int inloop = (nk > NSTG - 1) ? min(k + 1, nk - (NSTG - 1)) : 0;
        cp_wait(npre + inloop - (k + 1));
        __syncthreads();

        const uint32_t sAh = stage0 + s * STAGE_BYTES + 0 * TILE_BYTES;
        const uint32_t sAl = sAh + TILE_BYTES;
        const uint32_t sBh = sAh + 2 * TILE_BYTES;
        const uint32_t sBl = sAh + 3 * TILE_BYTES;

        #pragma unroll
        for (int ks = 0; ks < 2; ks++) {
            uint32_t ah[4][4], bh[2][4];
            #pragma unroll
            for (int mi = 0; mi < 4; mi++)
                ldsm4(ah[mi], sAh + sw64((uint32_t)((wm + mi * 16 + a_r) * 64 + ks * 32 + a_c)));
            #pragma unroll
            for (int p = 0; p < 2; p++)
                ldsm4(bh[p], sBh + sw64((uint32_t)((wn + p * 16 + b_r) * 64 + ks * 32 + b_c)));
            // term 1: Ah*Bh
            #pragma unroll
            for (int mi = 0; mi < 4; mi++)
                #pragma unroll
                for (int nj = 0; nj < 4; nj++)
                    mma_f16(acc[mi][nj], ah[mi], &bh[nj >> 1][(nj & 1) * 2]);
            // term 2: Al*Bh
            {
                uint32_t al[4][4];
                #pragma unroll
                for (int mi = 0; mi < 4; mi++)
                    ldsm4(al[mi], sAl + sw64((uint32_t)((wm + mi * 16 + a_r) * 64 + ks * 32 + a_c)));
                #pragma unroll
                for (int mi = 0; mi < 4; mi++)
                    #pragma unroll
                    for (int nj = 0; nj < 4; nj++)
                        mma_f16(acc[mi][nj], al[mi], &bh[nj >> 1][(nj & 1) * 2]);
            }
            // term 3: Ah*Bl
            {
                uint32_t bl[2][4];
                #pragma unroll
                for (int p = 0; p < 2; p++)
                    ldsm4(bl[p], sBl + sw64((uint32_t)((wn + p * 16 + b_r) * 64 + ks * 32 + b_c)));
                #pragma unroll
                for (int mi = 0; mi < 4; mi++)
                    #pragma unroll
                    for (int nj = 0; nj < 4; nj++)
                        mma_f16(acc[mi][nj], ah[mi], &bl[nj >> 1][(nj & 1) * 2]);
            }
        }
        __syncthreads();
    }

    // ---- epilogue ----
    #pragma unroll
    for (int mi = 0; mi < 4; mi++) {
        const int r0 = row0 + wm + mi * 16 + (lane >> 2);
        #pragma unroll
        for (int nj = 0; nj < 4; nj++) {
            const int c = col0 + wn + nj * 8 + (lane & 3) * 2;
            float v0 = acc[mi][nj][0], v1 = acc[mi][nj][1];
            float v2 = acc[mi][nj][2], v3 = acc[mi][nj][3];
            if (BIAS) {
                float b0 = bias[c], b1 = bias[c + 1];
                v0 += b0; v1 += b1; v2 += b0; v3 += b1;
            }
            if (EPI == 0 || EPI == 2) {
                float* cp = Cf + (long long)z * cB + (long long)r0 * ldC + c;
                *(float2*)cp = make_float2(v0, v1);
                *(float2*)(cp + 8LL * ldC) = make_float2(v2, v3);
            }
            if (EPI >= 1) {
                __half h0, l0, h1, l1;
                split1(v0, h0, l0); split1(v1, h1, l1);
                __half* hp = Chi + (long long)z * cB + (long long)r0 * ldC + c;
                __half* lp = Clo + (long long)z * cB + (long long)r0 * ldC + c;
                *(__half2*)hp = __halves2half2(h0, h1);
                *(__half2*)lp = __halves2half2(l0, l1);
                split1(v2, h0, l0); split1(v3, h1, l1);
                *(__half2*)(hp + 8LL * ldC) = __halves2half2(h0, h1);
                *(__half2*)(lp + 8LL * ldC) = __halves2half2(l0, l1);
            }
        }
    }
}

// ---------------------------------------------------------------------------
// elementwise fp32 -> fp16 hi/lo split
// ---------------------------------------------------------------------------
__global__ void split_kernel(const float* __restrict__ in,
                             __half* __restrict__ hi,
                             __half* __restrict__ lo, int n4)
{
    int i = blockIdx.x * blockDim.x + threadIdx.x;
    if (i >= n4) return;
    float4 v = ((const float4*)in)[i];
    __half h0, l0, h1, l1, h2, l2, h3, l3;
    split1(v.x, h0, l0); split1(v.y, h1, l1);
    split1(v.z, h2, l2); split1(v.w, h3, l3);
    __half2 ha = __halves2half2(h0, h1), hb = __halves2half2(h2, h3);
    __half2 la = __halves2half2(l0, l1), lb = __halves2half2(l2, l3);
    ((uint2*)hi)[i] = make_uint2(*(uint32_t*)&ha, *(uint32_t*)&hb);
    ((uint2*)lo)[i] = make_uint2(*(uint32_t*)&la, *(uint32_t*)&lb);
}

// transpose + split: fp32 [Z][R][C] -> fp16 hi/lo [Z][C][R]
__global__ void tsplit_kernel(const float* __restrict__ in,
                              __half* __restrict__ hi,
                              __half* __restrict__ lo, int R, int C)
{
    __shared__ float t[32][33];
    const long long zoff = (long long)blockIdx.z * R * C;
    const int c0 = blockIdx.x * 32, r0 = blockIdx.y * 32;
    const int tx = threadIdx.x, ty = threadIdx.y;
    #pragma unroll
    for (int i = 0; i < 4; i++)
        t[ty + 8 * i][tx] = in[zoff + (long long)(r0 + ty + 8 * i) * C + c0 + tx];
    __syncthreads();
    #pragma unroll
    for (int i = 0; i < 4; i++) {
        float v = t[tx][ty + 8 * i];
        __half h, l; split1(v, h, l);
        long long o = zoff + (long long)(c0 + ty + 8 * i) * R + r0 + tx;
        hi[o] = h; lo[o] = l;
    }
}

// ---------------------------------------------------------------------------
// causal softmax fp32 scores -> fp16 hi/lo probs; exp cached in registers.
// zero-fill to end of the diagonal 128-block (PV GEMM never reads beyond).
// ---------------------------------------------------------------------------
__global__ __launch_bounds__(256)
void softmax_causal_kernel(const float* __restrict__ S,
                           __half* __restrict__ Phi,
                           __half* __restrict__ Plo)
{
    const int q = blockIdx.x, b = blockIdx.y;
    const long long off = ((long long)b * SEQ + q) * SEQ;
    const float* row = S + off;
    const int n = q + 1;
    const int tid = threadIdx.x;
    __shared__ float sh[8];

    float rv[8];
    int cnt = 0;
    float m = -INFINITY;
    for (int i = tid; i < n; i += 256) {
        float v = row[i];
        rv[cnt++] = v;
        m = fmaxf(m, v);
    }
    #pragma unroll
    for (int o = 16; o; o >>= 1) m = fmaxf(m, __shfl_xor_sync(0xffffffffu, m, o));
    if ((tid & 31) == 0) sh[tid >> 5] = m;
    __syncthreads();
    float mr = sh[0];
    #pragma unroll
    for (int i = 1; i < 8; i++) mr = fmaxf(mr, sh[i]);
    __syncthreads();

    float s = 0.0f;
    #pragma unroll
    for (int j = 0; j < 8; j++)
        if (j < cnt) { rv[j] = __expf(rv[j] - mr); s += rv[j]; }
    #pragma unroll
    for (int o = 16; o; o >>= 1) s += __shfl_xor_sync(0xffffffffu, s, o);
    if ((tid & 31) == 0) sh[tid >> 5] = s;
    __syncthreads();
    float sr = 0.0f;
    #pragma unroll
    for (int i = 0; i < 8; i++) sr += sh[i];
    const float inv = 1.0f / sr;

    cnt = 0;
    for (int i = tid; i < n; i += 256) {
        float p = rv[cnt++] * inv;
        __half h, l; split1(p, h, l);
        Phi[off + i] = h; Plo[off + i] = l;
    }
    const int fend = ((q >> 7) + 1) << 7;   // end of diagonal 128-block
    const __half z16 = __float2half(0.0f);
    for (int i = n + tid; i < fend; i += 256) {
        Phi[off + i] = z16; Plo[off + i] = z16;
    }
}

// ---------------------------------------------------------------------------
extern "C" void kernel_launch(void* const* d_in, const int* in_sizes, int n_in,
                              void* d_out, int out_size)
{
    const float* x_batch = (const float*)d_in[0];
    const float* lin_w   = (const float*)d_in[1];
    const float* lin_b   = (const float*)d_in[2];
    const float* W_q     = (const float*)d_in[3];
    const float* W_k     = (const float*)d_in[4];
    const float* W_v     = (const float*)d_in[5];

    float* outF = (float*)d_out;
    float* outK = outF + (long long)BS * DIM;
    float* outV = outK + (long long)BS * DIM;

    __half *xb_hi, *xb_lo, *x_hi, *x_lo, *q_hi, *q_lo, *k_hi, *k_lo;
    __half *vt_hi, *vt_lo, *p_hi, *p_lo;
    __half *lw_hi, *lw_lo, *wq_hi, *wq_lo, *wk_hi, *wk_lo, *wv_hi, *wv_lo;
    float* ss;
    cudaGetSymbolAddress((void**)&xb_hi, g_xb_hi); cudaGetSymbolAddress((void**)&xb_lo, g_xb_lo);
    cudaGetSymbolAddress((void**)&x_hi,  g_x_hi);  cudaGetSymbolAddress((void**)&x_lo,  g_x_lo);
    cudaGetSymbolAddress((void**)&q_hi,  g_q_hi);  cudaGetSymbolAddress((void**)&q_lo,  g_q_lo);
    cudaGetSymbolAddress((void**)&k_hi,  g_k_hi);  cudaGetSymbolAddress((void**)&k_lo,  g_k_lo);
    cudaGetSymbolAddress((void**)&vt_hi, g_vt_hi); cudaGetSymbolAddress((void**)&vt_lo, g_vt_lo);
    cudaGetSymbolAddress((void**)&p_hi,  g_p_hi);  cudaGetSymbolAddress((void**)&p_lo,  g_p_lo);
    cudaGetSymbolAddress((void**)&lw_hi, g_lw_hi); cudaGetSymbolAddress((void**)&lw_lo, g_lw_lo);
    cudaGetSymbolAddress((void**)&wq_hi, g_wq_hi); cudaGetSymbolAddress((void**)&wq_lo, g_wq_lo);
    cudaGetSymbolAddress((void**)&wk_hi, g_wk_hi); cudaGetSymbolAddress((void**)&wk_lo, g_wk_lo);
    cudaGetSymbolAddress((void**)&wv_hi, g_wv_hi); cudaGetSymbolAddress((void**)&wv_lo, g_wv_lo);
    cudaGetSymbolAddress((void**)&ss, g_s);

    cudaFuncSetAttribute(gemm_mma<1, true,  false, false>, cudaFuncAttributeMaxDynamicSharedMemorySize, SMEM_DYN);
    cudaFuncSetAttribute(gemm_mma<1, false, false, false>, cudaFuncAttributeMaxDynamicSharedMemorySize, SMEM_DYN);
    cudaFuncSetAttribute(gemm_mma<2, false, false, false>, cudaFuncAttributeMaxDynamicSharedMemorySize, SMEM_DYN);
    cudaFuncSetAttribute(gemm_mma<0, false, false, false>, cudaFuncAttributeMaxDynamicSharedMemorySize, SMEM_DYN);
    cudaFuncSetAttribute(gemm_mma<0, false, true,  false>, cudaFuncAttributeMaxDynamicSharedMemorySize, SMEM_DYN);
    cudaFuncSetAttribute(gemm_mma<0, false, false, true >, cudaFuncAttributeMaxDynamicSharedMemorySize, SMEM_DYN);

    // ---- input splits ----
    split_kernel<<<(BS * DIM / 4 + 255) / 256, 256>>>(x_batch, xb_hi, xb_lo, BS * DIM / 4);
    split_kernel<<<(DIM * DIM / 4 + 255) / 256, 256>>>(lin_w, lw_hi, lw_lo, DIM * DIM / 4);
    {
        dim3 g(DIM / 32, DIM / 32, 1), t(32, 8);
        tsplit_kernel<<<g, t>>>(W_q, wq_hi, wq_lo, DIM, DIM);
        tsplit_kernel<<<g, t>>>(W_k, wk_hi, wk_lo, DIM, DIM);
        tsplit_kernel<<<g, t>>>(W_v, wv_hi, wv_lo, DIM, DIM);
    }

    // ---- G1: x = x_batch @ lin_w^T + b  -> fp16 split ----
    {
        dim3 g(DIM / 128, BS / 128, 1);
        gemm_mma<1, true, false, false><<<g, 256, SMEM_DYN>>>(
            xb_hi, xb_lo, lw_hi, lw_lo, lin_b,
            nullptr, x_hi, x_lo, DIM, DIM, 0, 0, 0);
    }
    // ---- G2/3/4: Q (split), K (f32 cache + split), V (f32 cache) ----
    {
        dim3 g(DIM / 128, BS / 128, 1);
        gemm_mma<1, false, false, false><<<g, 256, SMEM_DYN>>>(
            x_hi, x_lo, wq_hi, wq_lo, nullptr,
            nullptr, q_hi, q_lo, DIM, DIM, 0, 0, 0);
        gemm_mma<2, false, false, false><<<g, 256, SMEM_DYN>>>(
            x_hi, x_lo, wk_hi, wk_lo, nullptr,
            outK, k_hi, k_lo, DIM, DIM, 0, 0, 0);
        gemm_mma<0, false, false, false><<<g, 256, SMEM_DYN>>>(
            x_hi, x_lo, wv_hi, wv_lo, nullptr,
            outV, nullptr, nullptr, DIM, DIM, 0, 0, 0);
    }
    // ---- V transpose+split: [8][2048][1024] -> [8][1024][2048] ----
    {
        dim3 g(DIM / 32, SEQ / 32, BATCH), t(32, 8);
        tsplit_kernel<<<g, t>>>(outV, vt_hi, vt_lo, SEQ, DIM);
    }
    // ---- G5: scores = Q @ K^T (batched, causal block skip) ----
    {
        dim3 g(SEQ / 128, SEQ / 128, BATCH);
        gemm_mma<0, false, true, false><<<g, 256, SMEM_DYN>>>(
            q_hi, q_lo, k_hi, k_lo, nullptr,
            ss, nullptr, nullptr, DIM, SEQ,
            (long long)SEQ * DIM, (long long)SEQ * DIM, (long long)SEQ * SEQ);
    }
    // ---- softmax -> fp16 split probs ----
    {
        dim3 g(SEQ, BATCH);
        softmax_causal_kernel<<<g, 256>>>(ss, p_hi, p_lo);
    }
    // ---- G6: F = P @ V^T-layout (batched, causal K-limit) ----
    {
        dim3 g(DIM / 128, SEQ / 128, BATCH);
        gemm_mma<0, false, false, true><<<g, 256, SMEM_DYN>>>(
            p_hi, p_lo, vt_hi, vt_lo, nullptr,
            outF, nullptr, nullptr, SEQ, DIM,
            (long long)SEQ * SEQ, (long long)DIM * SEQ, (long long)SEQ * DIM);
    }
}

// round 5
// speedup vs baseline: 3.5823x; 1.1914x over previous
#include <cuda_runtime.h>
#include <cuda_fp16.h>
#include <math.h>
#include <stdint.h>

#define BATCH 8
#define SEQ   2048
#define DIM   1024
#define BS    (BATCH * SEQ)   // 16384

// ---------------------------------------------------------------------------
// Scratch (__device__ globals: allocation-free rule)
// ---------------------------------------------------------------------------
__device__ __half g_xb_hi[BS * DIM], g_xb_lo[BS * DIM];
__device__ __half g_wT_hi[3 * DIM * DIM], g_wT_lo[3 * DIM * DIM];   // WqT,WkT,WvT [h][e]
__device__ __half g_lwT_hi[DIM * DIM], g_lwT_lo[DIM * DIM];          // lwT [d][e]
__device__ __half g_c_hi[3 * DIM * DIM], g_c_lo[3 * DIM * DIM];      // combined W' [h][d]
__device__ float  g_bias[3 * DIM];                                   // bq,bk,bv
__device__ __half g_qkv_hi[3LL * BS * DIM], g_qkv_lo[3LL * BS * DIM];
__device__ __half g_vt_hi[(long long)BATCH * DIM * SEQ], g_vt_lo[(long long)BATCH * DIM * SEQ];
__device__ __half g_p_hi [(long long)BATCH * SEQ * SEQ], g_p_lo [(long long)BATCH * SEQ * SEQ];
__device__ float  g_s[(long long)BATCH * SEQ * SEQ];

// ---------------------------------------------------------------------------
// helpers
// ---------------------------------------------------------------------------
__device__ __forceinline__ uint32_t smem_u32(const void* p) {
    uint32_t a;
    asm("{ .reg .u64 t; cvta.to.shared.u64 t, %1; cvt.u32.u64 %0, t; }"
        : "=r"(a) : "l"(p));
    return a;
}

__device__ __forceinline__ void cp16(uint32_t saddr, const void* gaddr) {
    asm volatile("cp.async.cg.shared.global [%0], [%1], 16;" :: "r"(saddr), "l"(gaddr));
}
__device__ __forceinline__ void cp_commit() {
    asm volatile("cp.async.commit_group;" ::: "memory");
}
__device__ __forceinline__ void cp_wait(int n) {
    if (n <= 0)      asm volatile("cp.async.wait_group 0;" ::: "memory");
    else if (n == 1) asm volatile("cp.async.wait_group 1;" ::: "memory");
    else             asm volatile("cp.async.wait_group 2;" ::: "memory");
}

__device__ __forceinline__ void ldsm4(uint32_t (&r)[4], uint32_t addr) {
    asm volatile("ldmatrix.sync.aligned.m8n8.x4.shared.b16 {%0,%1,%2,%3}, [%4];"
        : "=r"(r[0]), "=r"(r[1]), "=r"(r[2]), "=r"(r[3]) : "r"(addr));
}

__device__ __forceinline__ void mma_f16(float* c, const uint32_t* a, const uint32_t* b) {
    asm volatile("mma.sync.aligned.m16n8k16.row.col.f32.f16.f16.f32 "
        "{%0,%1,%2,%3}, {%4,%5,%6,%7}, {%8,%9}, {%0,%1,%2,%3};"
        : "+f"(c[0]), "+f"(c[1]), "+f"(c[2]), "+f"(c[3])
        : "r"(a[0]), "r"(a[1]), "r"(a[2]), "r"(a[3]), "r"(b[0]), "r"(b[1]));
}

// SW64 swizzle for 64B rows — conflict-free ldmatrix
__device__ __forceinline__ uint32_t sw64(uint32_t off) {
    return off ^ ((off >> 3) & 0x30);
}

__device__ __forceinline__ void split1(float v, __half& h, __half& l) {
    h = __float2half(v);
    l = __float2half(v - __half2float(h));
}

// ---------------------------------------------------------------------------
// split-fp16 GEMM on HMMA: C[M,N](fp32) = (Ahi+Alo)[M,K] * (Bhi+Blo)[N,K]^T
// TERMS=3: Ah*Bh + Al*Bh + Ah*Bl ;  TERMS=2: Ah*Bh + Al*Bh
// 128x128 CTA tile, BK=32, 3-stage cp.async, 256 threads, 2 CTAs/SM (96KB).
// EPI: 0 = fp32 out, 1 = fp16 hi/lo split out, 2 = both
// ---------------------------------------------------------------------------
#define NSTG 3
#define TILE_BYTES  8192                  // 128 rows x 64B (32 halves)
#define STAGE_BYTES (4 * TILE_BYTES)      // Ahi, Alo, Bhi, Blo  = 32KB
#define SMEM_DYN    (NSTG * STAGE_BYTES + 1024)   // 99328

// load one 128x32 fp16 tile, SW64-swizzled (2 cp.async per thread)
__device__ __forceinline__ void load_tile(const __half* __restrict__ g,
                                          int row0, int k0, int ld,
                                          uint32_t sdst, int tid) {
    #pragma unroll
    for (int i = 0; i < 2; i++) {
        int gr = i * 256 + tid;          // 0..511
        int r  = gr >> 2;                // tile row 0..127
        int sec = gr & 3;                // 16B sector 0..3
        cp16(sdst + sw64((uint32_t)(r * 64 + sec * 16)),
             (const void*)(g + (long long)(row0 + r) * ld + (k0 + sec * 8)));
    }
}

template<int EPI, bool BIAS, bool CAUSAL, bool KLIM, int TERMS>
__global__ void __launch_bounds__(256, 2)
gemm_mma(const __half* __restrict__ Ahi, const __half* __restrict__ Alo,
         const __half* __restrict__ Bhi, const __half* __restrict__ Blo,
         const float* __restrict__ bias,
         float* __restrict__ Cf, __half* __restrict__ Chi, __half* __restrict__ Clo,
         int K, int ldC,
         long long aB, long long bB, long long cB)
{
    const int bx = blockIdx.x, z = blockIdx.z;
    int by = blockIdx.y;
    if (CAUSAL && bx > by) return;
    if (KLIM) by = gridDim.y - 1 - by;    // longest tiles first

    extern __shared__ char smem[];
    const uint32_t stage0 = (smem_u32(smem) + 1023u) & ~1023u;

    const int tid  = threadIdx.x;
    const int lane = tid & 31;
    const int wid  = tid >> 5;
    const int wm   = (wid & 1) * 64;     // warp m offset in tile
    const int wn   = (wid >> 1) * 32;    // warp n offset in tile

    const __half* A_hi = Ahi + (long long)z * aB;
    const __half* A_lo = Alo + (long long)z * aB;
    const __half* B_hi = Bhi + (long long)z * bB;
    const __half* B_lo = Blo + (long long)z * bB;

    int nk = K >> 5;
    if (KLIM) { int lim = 4 * (by + 1); if (lim < nk) nk = lim; }
    const int row0 = by * 128;
    const int col0 = bx * 128;

    float acc[4][4][4];
    #pragma unroll
    for (int i = 0; i < 4; i++)
        #pragma unroll
        for (int j = 0; j < 4; j++)
            #pragma unroll
            for (int c = 0; c < 4; c++) acc[i][j][c] = 0.0f;

    // per-lane ldmatrix address components
    const int a_r = ((lane >> 3) & 1) * 8 + (lane & 7);   // + mi*16 + wm
    const int a_c = (lane >> 4) * 16;                      // + ks*32
    const int b_r = ((lane >> 4) & 1) * 8 + (lane & 7);    // + pair*16 + wn
    const int b_c = ((lane >> 3) & 1) * 16;                // + ks*32

    // prologue
    const int npre = (NSTG - 1 < nk) ? NSTG - 1 : nk;
    for (int c = 0; c < npre; c++) {
        uint32_t st = stage0 + c * STAGE_BYTES;
        load_tile(A_hi, row0, c * 32, K, st + 0 * TILE_BYTES, tid);
        load_tile(A_lo, row0, c * 32, K, st + 1 * TILE_BYTES, tid);
        load_tile(B_hi, col0, c * 32, K, st + 2 * TILE_BYTES, tid);
        if (TERMS >= 3)
            load_tile(B_lo, col0, c * 32, K, st + 3 * TILE_BYTES, tid);
        cp_commit();
    }

    for (int k = 0; k < nk; k++) {
        const int s = k % NSTG;
        const int cl = k + NSTG - 1;
        if (cl < nk) {
            uint32_t st = stage0 + (cl % NSTG) * STAGE_BYTES;
            load_tile(A_hi, row0, cl * 32, K, st + 0 * TILE_BYTES, tid);
            load_tile(A_lo, row0, cl * 32, K, st + 1 * TILE_BYTES, tid);
            load_tile(B_hi, col0, cl * 32, K, st + 2 * TILE_BYTES, tid);
            if (TERMS >= 3)
                load_tile(B_lo, col0, cl * 32, K, st + 3 * TILE_BYTES, tid);
            cp_commit();
        }
        int inloop = (nk > NSTG - 1) ? min(k + 1, nk - (NSTG - 1)) : 0;
        cp_wait(npre + inloop - (k + 1));
        __syncthreads();

        const uint32_t sAh = stage0 + s * STAGE_BYTES + 0 * TILE_BYTES;
        const uint32_t sAl = sAh + TILE_BYTES;
        const uint32_t sBh = sAh + 2 * TILE_BYTES;
        const uint32_t sBl = sAh + 3 * TILE_BYTES;

        #pragma unroll
        for (int ks = 0; ks < 2; ks++) {
            uint32_t ah[4][4], bh[2][4];
            #pragma unroll
            for (int mi = 0; mi < 4; mi++)
                ldsm4(ah[mi], sAh + sw64((uint32_t)((wm + mi * 16 + a_r) * 64 + ks * 32 + a_c)));
            #pragma unroll
            for (int p = 0; p < 2; p++)
                ldsm4(bh[p], sBh + sw64((uint32_t)((wn + p * 16 + b_r) * 64 + ks * 32 + b_c)));
            // term 1: Ah*Bh
            #pragma unroll
            for (int mi = 0; mi < 4; mi++)
                #pragma unroll
                for (int nj = 0; nj < 4; nj++)
                    mma_f16(acc[mi][nj], ah[mi], &bh[nj >> 1][(nj & 1) * 2]);
            // term 2: Al*Bh
            {
                uint32_t al[4][4];
                #pragma unroll
                for (int mi = 0; mi < 4; mi++)
                    ldsm4(al[mi], sAl + sw64((uint32_t)((wm + mi * 16 + a_r) * 64 + ks * 32 + a_c)));
                #pragma unroll
                for (int mi = 0; mi < 4; mi++)
                    #pragma unroll
                    for (int nj = 0; nj < 4; nj++)
                        mma_f16(acc[mi][nj], al[mi], &bh[nj >> 1][(nj & 1) * 2]);
            }
            // term 3: Ah*Bl
            if (TERMS >= 3) {
                uint32_t bl[2][4];
                #pragma unroll
                for (int p = 0; p < 2; p++)
                    ldsm4(bl[p], sBl + sw64((uint32_t)((wn + p * 16 + b_r) * 64 + ks * 32 + b_c)));
                #pragma unroll
                for (int mi = 0; mi < 4; mi++)
                    #pragma unroll
                    for (int nj = 0; nj < 4; nj++)
                        mma_f16(acc[mi][nj], ah[mi], &bl[nj >> 1][(nj & 1) * 2]);
            }
        }
        __syncthreads();
    }

    // ---- epilogue ----
    const float* bp = bias + (long long)z * DIM;   // only read when BIAS
    #pragma unroll
    for (int mi = 0; mi < 4; mi++) {
        const int r0 = row0 + wm + mi * 16 + (lane >> 2);
        #pragma unroll
        for (int nj = 0; nj < 4; nj++) {
            const int c = col0 + wn + nj * 8 + (lane & 3) * 2;
            float v0 = acc[mi][nj][0], v1 = acc[mi][nj][1];
            float v2 = acc[mi][nj][2], v3 = acc[mi][nj][3];
            if (BIAS) {
                float b0 = bp[c], b1 = bp[c + 1];
                v0 += b0; v1 += b1; v2 += b0; v3 += b1;
            }
            if (EPI == 0 || EPI == 2) {
                float* cp = Cf + (long long)z * cB + (long long)r0 * ldC + c;
                *(float2*)cp = make_float2(v0, v1);
                *(float2*)(cp + 8LL * ldC) = make_float2(v2, v3);
            }
            if (EPI >= 1) {
                __half h0, l0, h1, l1;
                split1(v0, h0, l0); split1(v1, h1, l1);
                __half* hp = Chi + (long long)z * cB + (long long)r0 * ldC + c;
                __half* lp = Clo + (long long)z * cB + (long long)r0 * ldC + c;
                *(__half2*)hp = __halves2half2(h0, h1);
                *(__half2*)lp = __halves2half2(l0, l1);
                split1(v2, h0, l0); split1(v3, h1, l1);
                *(__half2*)(hp + 8LL * ldC) = __halves2half2(h0, h1);
                *(__half2*)(lp + 8LL * ldC) = __halves2half2(l0, l1);
            }
        }
    }
}

// ---------------------------------------------------------------------------
// elementwise fp32 -> fp16 hi/lo split
// ---------------------------------------------------------------------------
__global__ void split_kernel(const float* __restrict__ in,
                             __half* __restrict__ hi,
                             __half* __restrict__ lo, int n4)
{
    int i = blockIdx.x * blockDim.x + threadIdx.x;
    if (i >= n4) return;
    float4 v = ((const float4*)in)[i];
    __half h0, l0, h1, l1, h2, l2, h3, l3;
    split1(v.x, h0, l0); split1(v.y, h1, l1);
    split1(v.z, h2, l2); split1(v.w, h3, l3);
    __half2 ha = __halves2half2(h0, h1), hb = __halves2half2(h2, h3);
    __half2 la = __halves2half2(l0, l1), lb = __halves2half2(l2, l3);
    ((uint2*)hi)[i] = make_uint2(*(uint32_t*)&ha, *(uint32_t*)&hb);
    ((uint2*)lo)[i] = make_uint2(*(uint32_t*)&la, *(uint32_t*)&lb);
}

// transpose + split: fp32 [Z][R][C] -> fp16 hi/lo [Z][C][R]
__global__ void tsplit_kernel(const float* __restrict__ in,
                              __half* __restrict__ hi,
                              __half* __restrict__ lo, int R, int C)
{
    __shared__ float t[32][33];
    const long long zoff = (long long)blockIdx.z * R * C;
    const int c0 = blockIdx.x * 32, r0 = blockIdx.y * 32;
    const int tx = threadIdx.x, ty = threadIdx.y;
    #pragma unroll
    for (int i = 0; i < 4; i++)
        t[ty + 8 * i][tx] = in[zoff + (long long)(r0 + ty + 8 * i) * C + c0 + tx];
    __syncthreads();
    #pragma unroll
    for (int i = 0; i < 4; i++) {
        float v = t[tx][ty + 8 * i];
        __half h, l; split1(v, h, l);
        long long o = zoff + (long long)(c0 + ty + 8 * i) * R + r0 + tx;
        hi[o] = h; lo[o] = l;
    }
}

// ---------------------------------------------------------------------------
// combined biases: out[j*DIM + h] = sum_e b[e] * W_j[e, h],  j in {q,k,v}
// ---------------------------------------------------------------------------
__global__ void bias_combine_kernel(const float* __restrict__ b,
                                    const float* __restrict__ Wq,
                                    const float* __restrict__ Wk,
                                    const float* __restrict__ Wv,
                                    float* __restrict__ out)
{
    const int h = blockIdx.x * 256 + threadIdx.x;
    const float* W = (blockIdx.y == 0) ? Wq : (blockIdx.y == 1) ? Wk : Wv;
    float s = 0.0f;
    #pragma unroll 8
    for (int e = 0; e < DIM; e++) s += b[e] * W[(long long)e * DIM + h];
    out[blockIdx.y * DIM + h] = s;
}

// ---------------------------------------------------------------------------
// causal softmax fp32 scores -> fp16 hi/lo probs; exp cached in registers.
// zero-fill to end of the diagonal 128-block (PV GEMM never reads beyond).
// ---------------------------------------------------------------------------
__global__ __launch_bounds__(256)
void softmax_causal_kernel(const float* __restrict__ S,
                           __half* __restrict__ Phi,
                           __half* __restrict__ Plo)
{
    const int q = blockIdx.x, b = blockIdx.y;
    const long long off = ((long long)b * SEQ + q) * SEQ;
    const float* row = S + off;
    const int n = q + 1;
    const int tid = threadIdx.x;
    __shared__ float sh[8];

    float rv[8];
    int cnt = 0;
    float m = -INFINITY;
    for (int i = tid; i < n; i += 256) {
        float v = row[i];
        rv[cnt++] = v;
        m = fmaxf(m, v);
    }
    #pragma unroll
    for (int o = 16; o; o >>= 1) m = fmaxf(m, __shfl_xor_sync(0xffffffffu, m, o));
    if ((tid & 31) == 0) sh[tid >> 5] = m;
    __syncthreads();
    float mr = sh[0];
    #pragma unroll
    for (int i = 1; i < 8; i++) mr = fmaxf(mr, sh[i]);
    __syncthreads();

    float s = 0.0f;
    #pragma unroll
    for (int j = 0; j < 8; j++)
        if (j < cnt) { rv[j] = __expf(rv[j] - mr); s += rv[j]; }
    #pragma unroll
    for (int o = 16; o; o >>= 1) s += __shfl_xor_sync(0xffffffffu, s, o);
    if ((tid & 31) == 0) sh[tid >> 5] = s;
    __syncthreads();
    float sr = 0.0f;
    #pragma unroll
    for (int i = 0; i < 8; i++) sr += sh[i];
    const float inv = 1.0f / sr;

    cnt = 0;
    for (int i = tid; i < n; i += 256) {
        float p = rv[cnt++] * inv;
        __half h, l; split1(p, h, l);
        Phi[off + i] = h; Plo[off + i] = l;
    }
    const int fend = ((q >> 7) + 1) << 7;   // end of diagonal 128-block
    const __half z16 = __float2half(0.0f);
    for (int i = n + tid; i < fend; i += 256) {
        Phi[off + i] = z16; Plo[off + i] = z16;
    }
}

// ---------------------------------------------------------------------------
extern "C" void kernel_launch(void* const* d_in, const int* in_sizes, int n_in,
                              void* d_out, int out_size)
{
    const float* x_batch = (const float*)d_in[0];
    const float* lin_w   = (const float*)d_in[1];
    const float* lin_b   = (const float*)d_in[2];
    const float* W_q     = (const float*)d_in[3];
    const float* W_k     = (const float*)d_in[4];
    const float* W_v     = (const float*)d_in[5];

    float* outF = (float*)d_out;
    float* outK = outF + (long long)BS * DIM;
    float* outV = outK + (long long)BS * DIM;

    __half *xb_hi, *xb_lo, *wT_hi, *wT_lo, *lwT_hi, *lwT_lo, *c_hi, *c_lo;
    __half *qkv_hi, *qkv_lo, *vt_hi, *vt_lo, *p_hi, *p_lo;
    float *bias3, *ss;
    cudaGetSymbolAddress((void**)&xb_hi, g_xb_hi); cudaGetSymbolAddress((void**)&xb_lo, g_xb_lo);
    cudaGetSymbolAddress((void**)&wT_hi, g_wT_hi); cudaGetSymbolAddress((void**)&wT_lo, g_wT_lo);
    cudaGetSymbolAddress((void**)&lwT_hi, g_lwT_hi); cudaGetSymbolAddress((void**)&lwT_lo, g_lwT_lo);
    cudaGetSymbolAddress((void**)&c_hi, g_c_hi);   cudaGetSymbolAddress((void**)&c_lo, g_c_lo);
    cudaGetSymbolAddress((void**)&bias3, g_bias);
    cudaGetSymbolAddress((void**)&qkv_hi, g_qkv_hi); cudaGetSymbolAddress((void**)&qkv_lo, g_qkv_lo);
    cudaGetSymbolAddress((void**)&vt_hi, g_vt_hi); cudaGetSymbolAddress((void**)&vt_lo, g_vt_lo);
    cudaGetSymbolAddress((void**)&p_hi,  g_p_hi);  cudaGetSymbolAddress((void**)&p_lo,  g_p_lo);
    cudaGetSymbolAddress((void**)&ss, g_s);

    cudaFuncSetAttribute(gemm_mma<1, false, false, false, 3>, cudaFuncAttributeMaxDynamicSharedMemorySize, SMEM_DYN);
    cudaFuncSetAttribute(gemm_mma<2, true,  false, false, 3>, cudaFuncAttributeMaxDynamicSharedMemorySize, SMEM_DYN);
    cudaFuncSetAttribute(gemm_mma<0, false, true,  false, 3>, cudaFuncAttributeMaxDynamicSharedMemorySize, SMEM_DYN);
    cudaFuncSetAttribute(gemm_mma<0, false, false, true,  2>, cudaFuncAttributeMaxDynamicSharedMemorySize, SMEM_DYN);

    const long long DD = (long long)DIM * DIM;

    // ---- input prep: split xb; transpose+split lw, Wq, Wk, Wv; biases ----
    split_kernel<<<(BS * DIM / 4 + 255) / 256, 256>>>(x_batch, xb_hi, xb_lo, BS * DIM / 4);
    {
        dim3 g(DIM / 32, DIM / 32, 1), t(32, 8);
        tsplit_kernel<<<g, t>>>(lin_w, lwT_hi, lwT_lo, DIM, DIM);     // lwT [d][e]
        tsplit_kernel<<<g, t>>>(W_q, wT_hi + 0 * DD, wT_lo + 0 * DD, DIM, DIM);  // WqT [h][e]
        tsplit_kernel<<<g, t>>>(W_k, wT_hi + 1 * DD, wT_lo + 1 * DD, DIM, DIM);
        tsplit_kernel<<<g, t>>>(W_v, wT_hi + 2 * DD, wT_lo + 2 * DD, DIM, DIM);
    }
    bias_combine_kernel<<<dim3(DIM / 256, 3), 256>>>(lin_b, W_q, W_k, W_v, bias3);

    // ---- combined weights: C_j[h][d] = sum_e W_j[e][h] * lw[e][d]  (z-batched) ----
    {
        dim3 g(DIM / 128, DIM / 128, 3);
        gemm_mma<1, false, false, false, 3><<<g, 256, SMEM_DYN>>>(
            wT_hi, wT_lo, lwT_hi, lwT_lo, nullptr,
            nullptr, c_hi, c_lo, DIM, DIM, DD, 0, DD);
    }
    // ---- Q/K/V = xb @ C_j^T + b_j  (one z-batched launch; EPI=2) ----
    // fp32 lands at outF(+z*BS*DIM): z=0 -> scratch in outF (overwritten by PV),
    // z=1 -> outK, z=2 -> outV. Splits land in qkv_{hi,lo}.
    {
        dim3 g(DIM / 128, BS / 128, 3);
        gemm_mma<2, true, false, false, 3><<<g, 256, SMEM_DYN>>>(
            xb_hi, xb_lo, c_hi, c_lo, bias3,
            outF, qkv_hi, qkv_lo, DIM, DIM,
            0, DD, (long long)BS * DIM);
    }
    // ---- V transpose+split: [8][2048][1024] -> [8][1024][2048] ----
    {
        dim3 g(DIM / 32, SEQ / 32, BATCH), t(32, 8);
        tsplit_kernel<<<g, t>>>(outV, vt_hi, vt_lo, SEQ, DIM);
    }
    // ---- scores = Q @ K^T (batched, causal block skip) ----
    {
        const __half* q_hi = qkv_hi;                       const __half* q_lo = qkv_lo;
        const __half* k_hi = qkv_hi + (long long)BS * DIM; const __half* k_lo = qkv_lo + (long long)BS * DIM;
        dim3 g(SEQ / 128, SEQ / 128, BATCH);
        gemm_mma<0, false, true, false, 3><<<g, 256, SMEM_DYN>>>(
            q_hi, q_lo, k_hi, k_lo, nullptr,
            ss, nullptr, nullptr, DIM, SEQ,
            (long long)SEQ * DIM, (long long)SEQ * DIM, (long long)SEQ * SEQ);
    }
    // ---- softmax -> fp16 split probs ----
    {
        dim3 g(SEQ, BATCH);
        softmax_causal_kernel<<<g, 256>>>(ss, p_hi, p_lo);
    }
    // ---- F = P @ V^T-layout (batched, causal K-limit, 2-term) ----
    {
        dim3 g(DIM / 128, SEQ / 128, BATCH);
        gemm_mma<0, false, false, true, 2><<<g, 256, SMEM_DYN>>>(
            p_hi, p_lo, vt_hi, vt_lo, nullptr,
            outF, nullptr, nullptr, SEQ, DIM,
            (long long)SEQ * SEQ, (long long)DIM * SEQ, (long long)SEQ * DIM);
    }
}

// round 6
// speedup vs baseline: 3.7262x; 1.0402x over previous
#include <cuda_runtime.h>
#include <cuda_fp16.h>
#include <math.h>
#include <stdint.h>

#define BATCH 8
#define SEQ   2048
#define DIM   1024
#define BS    (BATCH * SEQ)   // 16384

// ---------------------------------------------------------------------------
// Scratch (__device__ globals: allocation-free rule)
// ---------------------------------------------------------------------------
__device__ __half g_xb_hi[BS * DIM], g_xb_lo[BS * DIM];
__device__ __half g_wT_hi[3 * DIM * DIM], g_wT_lo[3 * DIM * DIM];   // WqT,WkT,WvT [h][e]
__device__ __half g_lwT_hi[DIM * DIM], g_lwT_lo[DIM * DIM];          // lwT [d][e]
__device__ __half g_c_hi[3 * DIM * DIM], g_c_lo[3 * DIM * DIM];      // combined W' [h][d]
__device__ float  g_bias[3 * DIM];                                   // bq,bk,bv
__device__ __half g_qkv_hi[3LL * BS * DIM], g_qkv_lo[3LL * BS * DIM];
__device__ __half g_vt_hi[(long long)BATCH * DIM * SEQ], g_vt_lo[(long long)BATCH * DIM * SEQ];
__device__ __half g_p_hi [(long long)BATCH * SEQ * SEQ], g_p_lo [(long long)BATCH * SEQ * SEQ];
__device__ float  g_s[(long long)BATCH * SEQ * SEQ];

// ---------------------------------------------------------------------------
// helpers
// ---------------------------------------------------------------------------
__device__ __forceinline__ uint32_t smem_u32(const void* p) {
    uint32_t a;
    asm("{ .reg .u64 t; cvta.to.shared.u64 t, %1; cvt.u32.u64 %0, t; }"
        : "=r"(a) : "l"(p));
    return a;
}

__device__ __forceinline__ void cp16(uint32_t saddr, const void* gaddr) {
    asm volatile("cp.async.cg.shared.global [%0], [%1], 16;" :: "r"(saddr), "l"(gaddr));
}
__device__ __forceinline__ void cp_commit() {
    asm volatile("cp.async.commit_group;" ::: "memory");
}
template<int N>
__device__ __forceinline__ void cp_wait_c() {
    asm volatile("cp.async.wait_group %0;" :: "n"(N) : "memory");
}

__device__ __forceinline__ void ldsm4(uint32_t (&r)[4], uint32_t addr) {
    asm volatile("ldmatrix.sync.aligned.m8n8.x4.shared.b16 {%0,%1,%2,%3}, [%4];"
        : "=r"(r[0]), "=r"(r[1]), "=r"(r[2]), "=r"(r[3]) : "r"(addr));
}

__device__ __forceinline__ void mma_f16(float* c, const uint32_t* a, const uint32_t* b) {
    asm volatile("mma.sync.aligned.m16n8k16.row.col.f32.f16.f16.f32 "
        "{%0,%1,%2,%3}, {%4,%5,%6,%7}, {%8,%9}, {%0,%1,%2,%3};"
        : "+f"(c[0]), "+f"(c[1]), "+f"(c[2]), "+f"(c[3])
        : "r"(a[0]), "r"(a[1]), "r"(a[2]), "r"(a[3]), "r"(b[0]), "r"(b[1]));
}

// SW64 swizzle for 64B rows — conflict-free ldmatrix
__device__ __forceinline__ uint32_t sw64(uint32_t off) {
    return off ^ ((off >> 3) & 0x30);
}

__device__ __forceinline__ void split1(float v, __half& h, __half& l) {
    h = __float2half(v);
    l = __float2half(v - __half2float(h));
}

// ---------------------------------------------------------------------------
// split-fp16 GEMM on HMMA: C[M,N](fp32) = (Ahi+Alo)[M,K] * (Bhi+Blo)[N,K]^T
// TERMS=3: Ah*Bh + Al*Bh + Ah*Bl ;  TERMS=2: Ah*Bh + Al*Bh
// 128x128 CTA tile, BK=32, 3-stage cp.async, 256 threads, 2 CTAs/SM (96KB).
// ONE barrier per k-chunk: [wait; barrier; MMA(k); prefetch(k+NSTG-1)].
// EPI: 0 = fp32 out, 1 = fp16 hi/lo split out, 2 = both
// SKIPZ0: suppress fp32 store for z==0 (Q slice of QKV batch)
// ---------------------------------------------------------------------------
#define NSTG 3
#define TILE_BYTES  8192                  // 128 rows x 64B (32 halves)
#define STAGE_BYTES (4 * TILE_BYTES)      // Ahi, Alo, Bhi, Blo  = 32KB
#define SMEM_DYN    (NSTG * STAGE_BYTES + 1024)   // 99328

// load one 128x32 fp16 tile, SW64-swizzled (2 cp.async per thread)
__device__ __forceinline__ void load_tile(const __half* __restrict__ g,
                                          int row0, int k0, int ld,
                                          uint32_t sdst, int tid) {
    #pragma unroll
    for (int i = 0; i < 2; i++) {
        int gr = i * 256 + tid;          // 0..511
        int r  = gr >> 2;                // tile row 0..127
        int sec = gr & 3;                // 16B sector 0..3
        cp16(sdst + sw64((uint32_t)(r * 64 + sec * 16)),
             (const void*)(g + (long long)(row0 + r) * ld + (k0 + sec * 8)));
    }
}

template<int EPI, bool BIAS, bool CAUSAL, bool KLIM, int TERMS, bool SKIPZ0>
__global__ void __launch_bounds__(256, 2)
gemm_mma(const __half* __restrict__ Ahi, const __half* __restrict__ Alo,
         const __half* __restrict__ Bhi, const __half* __restrict__ Blo,
         const float* __restrict__ bias,
         float* __restrict__ Cf, __half* __restrict__ Chi, __half* __restrict__ Clo,
         int K, int ldC,
         long long aB, long long bB, long long cB)
{
    const int bx = blockIdx.x, z = blockIdx.z;
    int by = blockIdx.y;
    if (CAUSAL && bx > by) return;
    if (KLIM) by = gridDim.y - 1 - by;    // longest tiles first

    extern __shared__ char smem[];
    const uint32_t stage0 = (smem_u32(smem) + 1023u) & ~1023u;

    const int tid  = threadIdx.x;
    const int lane = tid & 31;
    const int wid  = tid >> 5;
    const int wm   = (wid & 1) * 64;     // warp m offset in tile
    const int wn   = (wid >> 1) * 32;    // warp n offset in tile

    const __half* A_hi = Ahi + (long long)z * aB;
    const __half* A_lo = Alo + (long long)z * aB;
    const __half* B_hi = Bhi + (long long)z * bB;
    const __half* B_lo = Blo + (long long)z * bB;

    int nk = K >> 5;
    if (KLIM) { int lim = 4 * (by + 1); if (lim < nk) nk = lim; }
    const int row0 = by * 128;
    const int col0 = bx * 128;

    float acc[4][4][4];
    #pragma unroll
    for (int i = 0; i < 4; i++)
        #pragma unroll
        for (int j = 0; j < 4; j++)
            #pragma unroll
            for (int c = 0; c < 4; c++) acc[i][j][c] = 0.0f;

    // per-lane ldmatrix address components
    const int a_r = ((lane >> 3) & 1) * 8 + (lane & 7);   // + mi*16 + wm
    const int a_c = (lane >> 4) * 16;                      // + ks*32
    const int b_r = ((lane >> 4) & 1) * 8 + (lane & 7);    // + pair*16 + wn
    const int b_c = ((lane >> 3) & 1) * 16;                // + ks*32

    // prologue: NSTG-1 chunks in flight (nk >= 4 always here)
    #pragma unroll
    for (int c = 0; c < NSTG - 1; c++) {
        uint32_t st = stage0 + c * STAGE_BYTES;
        load_tile(A_hi, row0, c * 32, K, st + 0 * TILE_BYTES, tid);
        load_tile(A_lo, row0, c * 32, K, st + 1 * TILE_BYTES, tid);
        load_tile(B_hi, col0, c * 32, K, st + 2 * TILE_BYTES, tid);
        if (TERMS >= 3)
            load_tile(B_lo, col0, c * 32, K, st + 3 * TILE_BYTES, tid);
        cp_commit();
    }

    for (int k = 0; k < nk; k++) {
        const int s = k % NSTG;
        // wait chunk k: steady state <= NSTG-2 groups pending; tail: 0
        if (k < nk - 1) cp_wait_c<NSTG - 2>(); else cp_wait_c<0>();
        __syncthreads();

        const uint32_t sAh = stage0 + s * STAGE_BYTES + 0 * TILE_BYTES;
        const uint32_t sAl = sAh + TILE_BYTES;
        const uint32_t sBh = sAh + 2 * TILE_BYTES;
        const uint32_t sBl = sAh + 3 * TILE_BYTES;

        #pragma unroll
        for (int ks = 0; ks < 2; ks++) {
            uint32_t ah[4][4], bh[2][4];
            #pragma unroll
            for (int mi = 0; mi < 4; mi++)
                ldsm4(ah[mi], sAh + sw64((uint32_t)((wm + mi * 16 + a_r) * 64 + ks * 32 + a_c)));
            #pragma unroll
            for (int p = 0; p < 2; p++)
                ldsm4(bh[p], sBh + sw64((uint32_t)((wn + p * 16 + b_r) * 64 + ks * 32 + b_c)));
            // term 1: Ah*Bh
            #pragma unroll
            for (int mi = 0; mi < 4; mi++)
                #pragma unroll
                for (int nj = 0; nj < 4; nj++)
                    mma_f16(acc[mi][nj], ah[mi], &bh[nj >> 1][(nj & 1) * 2]);
            // term 2: Al*Bh
            {
                uint32_t al[4][4];
                #pragma unroll
                for (int mi = 0; mi < 4; mi++)
                    ldsm4(al[mi], sAl + sw64((uint32_t)((wm + mi * 16 + a_r) * 64 + ks * 32 + a_c)));
                #pragma unroll
                for (int mi = 0; mi < 4; mi++)
                    #pragma unroll
                    for (int nj = 0; nj < 4; nj++)
                        mma_f16(acc[mi][nj], al[mi], &bh[nj >> 1][(nj & 1) * 2]);
            }
            // term 3: Ah*Bl
            if (TERMS >= 3) {
                uint32_t bl[2][4];
                #pragma unroll
                for (int p = 0; p < 2; p++)
                    ldsm4(bl[p], sBl + sw64((uint32_t)((wn + p * 16 + b_r) * 64 + ks * 32 + b_c)));
                #pragma unroll
                for (int mi = 0; mi < 4; mi++)
                    #pragma unroll
                    for (int nj = 0; nj < 4; nj++)
                        mma_f16(acc[mi][nj], ah[mi], &bl[nj >> 1][(nj & 1) * 2]);
            }
        }

        // prefetch chunk k+NSTG-1 (safe: all warps passed this iter's barrier,
        // so no warp still reads the stage this write targets)
        const int cl = k + NSTG - 1;
        if (cl < nk) {
            uint32_t st = stage0 + (cl % NSTG) * STAGE_BYTES;
            load_tile(A_hi, row0, cl * 32, K, st + 0 * TILE_BYTES, tid);
            load_tile(A_lo, row0, cl * 32, K, st + 1 * TILE_BYTES, tid);
            load_tile(B_hi, col0, cl * 32, K, st + 2 * TILE_BYTES, tid);
            if (TERMS >= 3)
                load_tile(B_lo, col0, cl * 32, K, st + 3 * TILE_BYTES, tid);
            cp_commit();
        }
    }

    // ---- epilogue ----
    const float* bp = bias + (long long)z * DIM;   // only read when BIAS
    const bool doF32 = (EPI == 0 || EPI == 2) && !(SKIPZ0 && z == 0);
    #pragma unroll
    for (int mi = 0; mi < 4; mi++) {
        const int r0 = row0 + wm + mi * 16 + (lane >> 2);
        #pragma unroll
        for (int nj = 0; nj < 4; nj++) {
            const int c = col0 + wn + nj * 8 + (lane & 3) * 2;
            float v0 = acc[mi][nj][0], v1 = acc[mi][nj][1];
            float v2 = acc[mi][nj][2], v3 = acc[mi][nj][3];
            if (BIAS) {
                float b0 = bp[c], b1 = bp[c + 1];
                v0 += b0; v1 += b1; v2 += b0; v3 += b1;
            }
            if (doF32) {
                float* cp = Cf + (long long)z * cB + (long long)r0 * ldC + c;
                *(float2*)cp = make_float2(v0, v1);
                *(float2*)(cp + 8LL * ldC) = make_float2(v2, v3);
            }
            if (EPI >= 1) {
                __half h0, l0, h1, l1;
                split1(v0, h0, l0); split1(v1, h1, l1);
                __half* hp = Chi + (long long)z * cB + (long long)r0 * ldC + c;
                __half* lp = Clo + (long long)z * cB + (long long)r0 * ldC + c;
                *(__half2*)hp = __halves2half2(h0, h1);
                *(__half2*)lp = __halves2half2(l0, l1);
                split1(v2, h0, l0); split1(v3, h1, l1);
                *(__half2*)(hp + 8LL * ldC) = __halves2half2(h0, h1);
                *(__half2*)(lp + 8LL * ldC) = __halves2half2(l0, l1);
            }
        }
    }
}

// ---------------------------------------------------------------------------
// elementwise fp32 -> fp16 hi/lo split
// ---------------------------------------------------------------------------
__global__ void split_kernel(const float* __restrict__ in,
                             __half* __restrict__ hi,
                             __half* __restrict__ lo, int n4)
{
    int i = blockIdx.x * blockDim.x + threadIdx.x;
    if (i >= n4) return;
    float4 v = ((const float4*)in)[i];
    __half h0, l0, h1, l1, h2, l2, h3, l3;
    split1(v.x, h0, l0); split1(v.y, h1, l1);
    split1(v.z, h2, l2); split1(v.w, h3, l3);
    __half2 ha = __halves2half2(h0, h1), hb = __halves2half2(h2, h3);
    __half2 la = __halves2half2(l0, l1), lb = __halves2half2(l2, l3);
    ((uint2*)hi)[i] = make_uint2(*(uint32_t*)&ha, *(uint32_t*)&hb);
    ((uint2*)lo)[i] = make_uint2(*(uint32_t*)&la, *(uint32_t*)&lb);
}

// transpose + split: fp32 [Z][R][C] -> fp16 hi/lo [Z][C][R]
__global__ void tsplit_kernel(const float* __restrict__ in,
                              __half* __restrict__ hi,
                              __half* __restrict__ lo, int R, int C)
{
    __shared__ float t[32][33];
    const long long zoff = (long long)blockIdx.z * R * C;
    const int c0 = blockIdx.x * 32, r0 = blockIdx.y * 32;
    const int tx = threadIdx.x, ty = threadIdx.y;
    #pragma unroll
    for (int i = 0; i < 4; i++)
        t[ty + 8 * i][tx] = in[zoff + (long long)(r0 + ty + 8 * i) * C + c0 + tx];
    __syncthreads();
    #pragma unroll
    for (int i = 0; i < 4; i++) {
        float v = t[tx][ty + 8 * i];
        __half h, l; split1(v, h, l);
        long long o = zoff + (long long)(c0 + ty + 8 * i) * R + r0 + tx;
        hi[o] = h; lo[o] = l;
    }
}

// ---------------------------------------------------------------------------
// combined biases: out[j*DIM + h] = sum_e b[e] * W_j[e, h],  j in {q,k,v}
// ---------------------------------------------------------------------------
__global__ void bias_combine_kernel(const float* __restrict__ b,
                                    const float* __restrict__ Wq,
                                    const float* __restrict__ Wk,
                                    const float* __restrict__ Wv,
                                    float* __restrict__ out)
{
    const int h = blockIdx.x * 256 + threadIdx.x;
    const float* W = (blockIdx.y == 0) ? Wq : (blockIdx.y == 1) ? Wk : Wv;
    float s = 0.0f;
    #pragma unroll 8
    for (int e = 0; e < DIM; e++) s += b[e] * W[(long long)e * DIM + h];
    out[blockIdx.y * DIM + h] = s;
}

// ---------------------------------------------------------------------------
// causal softmax fp32 scores -> fp16 hi/lo probs; exp cached in registers.
// zero-fill to end of the diagonal 128-block (PV GEMM never reads beyond).
// ---------------------------------------------------------------------------
__global__ __launch_bounds__(256)
void softmax_causal_kernel(const float* __restrict__ S,
                           __half* __restrict__ Phi,
                           __half* __restrict__ Plo)
{
    const int q = blockIdx.x, b = blockIdx.y;
    const long long off = ((long long)b * SEQ + q) * SEQ;
    const float* row = S + off;
    const int n = q + 1;
    const int tid = threadIdx.x;
    __shared__ float sh[8];

    float rv[8];
    int cnt = 0;
    float m = -INFINITY;
    for (int i = tid; i < n; i += 256) {
        float v = row[i];
        rv[cnt++] = v;
        m = fmaxf(m, v);
    }
    #pragma unroll
    for (int o = 16; o; o >>= 1) m = fmaxf(m, __shfl_xor_sync(0xffffffffu, m, o));
    if ((tid & 31) == 0) sh[tid >> 5] = m;
    __syncthreads();
    float mr = sh[0];
    #pragma unroll
    for (int i = 1; i < 8; i++) mr = fmaxf(mr, sh[i]);
    __syncthreads();

    float s = 0.0f;
    #pragma unroll
    for (int j = 0; j < 8; j++)
        if (j < cnt) { rv[j] = __expf(rv[j] - mr); s += rv[j]; }
    #pragma unroll
    for (int o = 16; o; o >>= 1) s += __shfl_xor_sync(0xffffffffu, s, o);
    if ((tid & 31) == 0) sh[tid >> 5] = s;
    __syncthreads();
    float sr = 0.0f;
    #pragma unroll
    for (int i = 0; i < 8; i++) sr += sh[i];
    const float inv = 1.0f / sr;

    cnt = 0;
    for (int i = tid; i < n; i += 256) {
        float p = rv[cnt++] * inv;
        __half h, l; split1(p, h, l);
        Phi[off + i] = h; Plo[off + i] = l;
    }
    const int fend = ((q >> 7) + 1) << 7;   // end of diagonal 128-block
    const __half z16 = __float2half(0.0f);
    for (int i = n + tid; i < fend; i += 256) {
        Phi[off + i] = z16; Plo[off + i] = z16;
    }
}

// ---------------------------------------------------------------------------
extern "C" void kernel_launch(void* const* d_in, const int* in_sizes, int n_in,
                              void* d_out, int out_size)
{
    const float* x_batch = (const float*)d_in[0];
    const float* lin_w   = (const float*)d_in[1];
    const float* lin_b   = (const float*)d_in[2];
    const float* W_q     = (const float*)d_in[3];
    const float* W_k     = (const float*)d_in[4];
    const float* W_v     = (const float*)d_in[5];

    float* outF = (float*)d_out;
    float* outK = outF + (long long)BS * DIM;
    float* outV = outK + (long long)BS * DIM;

    __half *xb_hi, *xb_lo, *wT_hi, *wT_lo, *lwT_hi, *lwT_lo, *c_hi, *c_lo;
    __half *qkv_hi, *qkv_lo, *vt_hi, *vt_lo, *p_hi, *p_lo;
    float *bias3, *ss;
    cudaGetSymbolAddress((void**)&xb_hi, g_xb_hi); cudaGetSymbolAddress((void**)&xb_lo, g_xb_lo);
    cudaGetSymbolAddress((void**)&wT_hi, g_wT_hi); cudaGetSymbolAddress((void**)&wT_lo, g_wT_lo);
    cudaGetSymbolAddress((void**)&lwT_hi, g_lwT_hi); cudaGetSymbolAddress((void**)&lwT_lo, g_lwT_lo);
    cudaGetSymbolAddress((void**)&c_hi, g_c_hi);   cudaGetSymbolAddress((void**)&c_lo, g_c_lo);
    cudaGetSymbolAddress((void**)&bias3, g_bias);
    cudaGetSymbolAddress((void**)&qkv_hi, g_qkv_hi); cudaGetSymbolAddress((void**)&qkv_lo, g_qkv_lo);
    cudaGetSymbolAddress((void**)&vt_hi, g_vt_hi); cudaGetSymbolAddress((void**)&vt_lo, g_vt_lo);
    cudaGetSymbolAddress((void**)&p_hi,  g_p_hi);  cudaGetSymbolAddress((void**)&p_lo,  g_p_lo);
    cudaGetSymbolAddress((void**)&ss, g_s);

    cudaFuncSetAttribute(gemm_mma<1, false, false, false, 3, false>, cudaFuncAttributeMaxDynamicSharedMemorySize, SMEM_DYN);
    cudaFuncSetAttribute(gemm_mma<2, true,  false, false, 3, true >, cudaFuncAttributeMaxDynamicSharedMemorySize, SMEM_DYN);
    cudaFuncSetAttribute(gemm_mma<0, false, true,  false, 3, false>, cudaFuncAttributeMaxDynamicSharedMemorySize, SMEM_DYN);
    cudaFuncSetAttribute(gemm_mma<0, false, false, true,  2, false>, cudaFuncAttributeMaxDynamicSharedMemorySize, SMEM_DYN);

    const long long DD = (long long)DIM * DIM;

    // ---- input prep: split xb; transpose+split lw, Wq, Wk, Wv; biases ----
    split_kernel<<<(BS * DIM / 4 + 255) / 256, 256>>>(x_batch, xb_hi, xb_lo, BS * DIM / 4);
    {
        dim3 g(DIM / 32, DIM / 32, 1), t(32, 8);
        tsplit_kernel<<<g, t>>>(lin_w, lwT_hi, lwT_lo, DIM, DIM);     // lwT [d][e]
        tsplit_kernel<<<g, t>>>(W_q, wT_hi + 0 * DD, wT_lo + 0 * DD, DIM, DIM);  // WqT [h][e]
        tsplit_kernel<<<g, t>>>(W_k, wT_hi + 1 * DD, wT_lo + 1 * DD, DIM, DIM);
        tsplit_kernel<<<g, t>>>(W_v, wT_hi + 2 * DD, wT_lo + 2 * DD, DIM, DIM);
    }
    bias_combine_kernel<<<dim3(DIM / 256, 3), 256>>>(lin_b, W_q, W_k, W_v, bias3);

    // ---- combined weights: C_j[h][d] = sum_e W_j[e][h] * lw[e][d]  (z-batched) ----
    {
        dim3 g(DIM / 128, DIM / 128, 3);
        gemm_mma<1, false, false, false, 3, false><<<g, 256, SMEM_DYN>>>(
            wT_hi, wT_lo, lwT_hi, lwT_lo, nullptr,
            nullptr, c_hi, c_lo, DIM, DIM, DD, 0, DD);
    }
    // ---- Q/K/V = xb @ C_j^T + b_j  (one z-batched launch; EPI=2, skip z=0 fp32) ----
    {
        dim3 g(DIM / 128, BS / 128, 3);
        gemm_mma<2, true, false, false, 3, true><<<g, 256, SMEM_DYN>>>(
            xb_hi, xb_lo, c_hi, c_lo, bias3,
            outF, qkv_hi, qkv_lo, DIM, DIM,
            0, DD, (long long)BS * DIM);
    }
    // ---- V transpose+split: [8][2048][1024] -> [8][1024][2048] ----
    {
        dim3 g(DIM / 32, SEQ / 32, BATCH), t(32, 8);
        tsplit_kernel<<<g, t>>>(outV, vt_hi, vt_lo, SEQ, DIM);
    }
    // ---- scores = Q @ K^T (batched, causal block skip) ----
    {
        const __half* q_hi = qkv_hi;                       const __half* q_lo = qkv_lo;
        const __half* k_hi = qkv_hi + (long long)BS * DIM; const __half* k_lo = qkv_lo + (long long)BS * DIM;
        dim3 g(SEQ / 128, SEQ / 128, BATCH);
        gemm_mma<0, false, true, false, 3, false><<<g, 256, SMEM_DYN>>>(
            q_hi, q_lo, k_hi, k_lo, nullptr,
            ss, nullptr, nullptr, DIM, SEQ,
            (long long)SEQ * DIM, (long long)SEQ * DIM, (long long)SEQ * SEQ);
    }
    // ---- softmax -> fp16 split probs ----
    {
        dim3 g(SEQ, BATCH);
        softmax_causal_kernel<<<g, 256>>>(ss, p_hi, p_lo);
    }
    // ---- F = P @ V^T-layout (batched, causal K-limit, 2-term) ----
    {
        dim3 g(DIM / 128, SEQ / 128, BATCH);
        gemm_mma<0, false, false, true, 2, false><<<g, 256, SMEM_DYN>>>(
            p_hi, p_lo, vt_hi, vt_lo, nullptr,
            outF, nullptr, nullptr, SEQ, DIM,
            (long long)SEQ * SEQ, (long long)DIM * SEQ, (long long)SEQ * DIM);
    }
}

// round 7
// speedup vs baseline: 3.9221x; 1.0526x over previous
#include <cuda_runtime.h>
#include <cuda_fp16.h>
#include <math.h>
#include <stdint.h>

#define BATCH 8
#define SEQ   2048
#define DIM   1024
#define BS    (BATCH * SEQ)   // 16384

// ---------------------------------------------------------------------------
// Scratch (__device__ globals: allocation-free rule)
// ---------------------------------------------------------------------------
__device__ __half g_xb_hi[BS * DIM], g_xb_lo[BS * DIM];
__device__ __half g_wT_hi[3 * DIM * DIM], g_wT_lo[3 * DIM * DIM];   // WqT,WkT,WvT [h][e]
__device__ __half g_lwT_hi[DIM * DIM], g_lwT_lo[DIM * DIM];          // lwT [d][e]
__device__ __half g_c_hi[3 * DIM * DIM], g_c_lo[3 * DIM * DIM];      // combined W' [h][d]
__device__ float  g_bias[3 * DIM];                                   // bq,bk,bv
__device__ __half g_qkv_hi[2LL * BS * DIM], g_qkv_lo[2LL * BS * DIM];// Q,K splits
__device__ __half g_vt_hi[(long long)BATCH * DIM * SEQ], g_vt_lo[(long long)BATCH * DIM * SEQ];
__device__ __half g_p_hi [(long long)BATCH * SEQ * SEQ], g_p_lo [(long long)BATCH * SEQ * SEQ];
__device__ float  g_s[(long long)BATCH * SEQ * SEQ];

// ---------------------------------------------------------------------------
// helpers
// ---------------------------------------------------------------------------
__device__ __forceinline__ uint32_t smem_u32(const void* p) {
    uint32_t a;
    asm("{ .reg .u64 t; cvta.to.shared.u64 t, %1; cvt.u32.u64 %0, t; }"
        : "=r"(a) : "l"(p));
    return a;
}

__device__ __forceinline__ void cp16(uint32_t saddr, const void* gaddr) {
    asm volatile("cp.async.cg.shared.global [%0], [%1], 16;" :: "r"(saddr), "l"(gaddr));
}
__device__ __forceinline__ void cp_commit() {
    asm volatile("cp.async.commit_group;" ::: "memory");
}
template<int N>
__device__ __forceinline__ void cp_wait_c() {
    asm volatile("cp.async.wait_group %0;" :: "n"(N) : "memory");
}

__device__ __forceinline__ void ldsm4(uint32_t (&r)[4], uint32_t addr) {
    asm volatile("ldmatrix.sync.aligned.m8n8.x4.shared.b16 {%0,%1,%2,%3}, [%4];"
        : "=r"(r[0]), "=r"(r[1]), "=r"(r[2]), "=r"(r[3]) : "r"(addr));
}

__device__ __forceinline__ void mma_f16(float* c, const uint32_t* a, const uint32_t* b) {
    asm volatile("mma.sync.aligned.m16n8k16.row.col.f32.f16.f16.f32 "
        "{%0,%1,%2,%3}, {%4,%5,%6,%7}, {%8,%9}, {%0,%1,%2,%3};"
        : "+f"(c[0]), "+f"(c[1]), "+f"(c[2]), "+f"(c[3])
        : "r"(a[0]), "r"(a[1]), "r"(a[2]), "r"(a[3]), "r"(b[0]), "r"(b[1]));
}

// SW64 swizzle for 64B rows — conflict-free ldmatrix
__device__ __forceinline__ uint32_t sw64(uint32_t off) {
    return off ^ ((off >> 3) & 0x30);
}

__device__ __forceinline__ void split1(float v, __half& h, __half& l) {
    h = __float2half(v);
    l = __float2half(v - __half2float(h));
}

// ---------------------------------------------------------------------------
// split-fp16 GEMM on HMMA: C[M,N](fp32) = (Ahi+Alo)[M,K] * (Bhi+Blo)[N,K]^T
// TERMS=3: Ah*Bh + Al*Bh + Ah*Bl ;  TERMS=2: Ah*Bh + Al*Bh
// 128x128 CTA tile, BK=32, 3-stage cp.async, 256 threads, 2 CTAs/SM (96KB).
// ONE barrier per k-chunk.
// EPI: 0 = fp32 out, 1 = fp16 hi/lo split out, 2 = both
// SKIPZ0: suppress fp32 store for z==0
// ---------------------------------------------------------------------------
#define NSTG 3
#define TILE_BYTES  8192                  // 128 rows x 64B (32 halves)
#define STAGE_BYTES (4 * TILE_BYTES)      // Ahi, Alo, Bhi, Blo  = 32KB
#define SMEM_DYN    (NSTG * STAGE_BYTES + 1024)   // 99328

// load one 128x32 fp16 tile, SW64-swizzled (2 cp.async per thread)
__device__ __forceinline__ void load_tile(const __half* __restrict__ g,
                                          int row0, int k0, int ld,
                                          uint32_t sdst, int tid) {
    #pragma unroll
    for (int i = 0; i < 2; i++) {
        int gr = i * 256 + tid;          // 0..511
        int r  = gr >> 2;                // tile row 0..127
        int sec = gr & 3;                // 16B sector 0..3
        cp16(sdst + sw64((uint32_t)(r * 64 + sec * 16)),
             (const void*)(g + (long long)(row0 + r) * ld + (k0 + sec * 8)));
    }
}

template<int EPI, bool BIAS, bool CAUSAL, bool KLIM, int TERMS, bool SKIPZ0>
__global__ void __launch_bounds__(256, 2)
gemm_mma(const __half* __restrict__ Ahi, const __half* __restrict__ Alo,
         const __half* __restrict__ Bhi, const __half* __restrict__ Blo,
         const float* __restrict__ bias,
         float* __restrict__ Cf, __half* __restrict__ Chi, __half* __restrict__ Clo,
         int K, int ldC,
         long long aB, long long bB, long long cB)
{
    const int bx = blockIdx.x, z = blockIdx.z;
    int by = blockIdx.y;
    if (CAUSAL && bx > by) return;
    if (KLIM) by = gridDim.y - 1 - by;    // longest tiles first

    extern __shared__ char smem[];
    const uint32_t stage0 = (smem_u32(smem) + 1023u) & ~1023u;

    const int tid  = threadIdx.x;
    const int lane = tid & 31;
    const int wid  = tid >> 5;
    const int wm   = (wid & 1) * 64;     // warp m offset in tile
    const int wn   = (wid >> 1) * 32;    // warp n offset in tile

    const __half* A_hi = Ahi + (long long)z * aB;
    const __half* A_lo = Alo + (long long)z * aB;
    const __half* B_hi = Bhi + (long long)z * bB;
    const __half* B_lo = Blo + (long long)z * bB;

    int nk = K >> 5;
    if (KLIM) { int lim = 4 * (by + 1); if (lim < nk) nk = lim; }
    const int row0 = by * 128;
    const int col0 = bx * 128;

    float acc[4][4][4];
    #pragma unroll
    for (int i = 0; i < 4; i++)
        #pragma unroll
        for (int j = 0; j < 4; j++)
            #pragma unroll
            for (int c = 0; c < 4; c++) acc[i][j][c] = 0.0f;

    // per-lane ldmatrix address components
    const int a_r = ((lane >> 3) & 1) * 8 + (lane & 7);   // + mi*16 + wm
    const int a_c = (lane >> 4) * 16;                      // + ks*32
    const int b_r = ((lane >> 4) & 1) * 8 + (lane & 7);    // + pair*16 + wn
    const int b_c = ((lane >> 3) & 1) * 16;                // + ks*32

    // prologue: NSTG-1 chunks in flight (nk >= 4 always here)
    #pragma unroll
    for (int c = 0; c < NSTG - 1; c++) {
        uint32_t st = stage0 + c * STAGE_BYTES;
        load_tile(A_hi, row0, c * 32, K, st + 0 * TILE_BYTES, tid);
        load_tile(A_lo, row0, c * 32, K, st + 1 * TILE_BYTES, tid);
        load_tile(B_hi, col0, c * 32, K, st + 2 * TILE_BYTES, tid);
        if (TERMS >= 3)
            load_tile(B_lo, col0, c * 32, K, st + 3 * TILE_BYTES, tid);
        cp_commit();
    }

    for (int k = 0; k < nk; k++) {
        const int s = k % NSTG;
        if (k < nk - 1) cp_wait_c<NSTG - 2>(); else cp_wait_c<0>();
        __syncthreads();

        const uint32_t sAh = stage0 + s * STAGE_BYTES + 0 * TILE_BYTES;
        const uint32_t sAl = sAh + TILE_BYTES;
        const uint32_t sBh = sAh + 2 * TILE_BYTES;
        const uint32_t sBl = sAh + 3 * TILE_BYTES;

        #pragma unroll
        for (int ks = 0; ks < 2; ks++) {
            uint32_t ah[4][4], bh[2][4];
            #pragma unroll
            for (int mi = 0; mi < 4; mi++)
                ldsm4(ah[mi], sAh + sw64((uint32_t)((wm + mi * 16 + a_r) * 64 + ks * 32 + a_c)));
            #pragma unroll
            for (int p = 0; p < 2; p++)
                ldsm4(bh[p], sBh + sw64((uint32_t)((wn + p * 16 + b_r) * 64 + ks * 32 + b_c)));
            // term 1: Ah*Bh
            #pragma unroll
            for (int mi = 0; mi < 4; mi++)
                #pragma unroll
                for (int nj = 0; nj < 4; nj++)
                    mma_f16(acc[mi][nj], ah[mi], &bh[nj >> 1][(nj & 1) * 2]);
            // term 2: Al*Bh
            {
                uint32_t al[4][4];
                #pragma unroll
                for (int mi = 0; mi < 4; mi++)
                    ldsm4(al[mi], sAl + sw64((uint32_t)((wm + mi * 16 + a_r) * 64 + ks * 32 + a_c)));
                #pragma unroll
                for (int mi = 0; mi < 4; mi++)
                    #pragma unroll
                    for (int nj = 0; nj < 4; nj++)
                        mma_f16(acc[mi][nj], al[mi], &bh[nj >> 1][(nj & 1) * 2]);
            }
            // term 3: Ah*Bl
            if (TERMS >= 3) {
                uint32_t bl[2][4];
                #pragma unroll
                for (int p = 0; p < 2; p++)
                    ldsm4(bl[p], sBl + sw64((uint32_t)((wn + p * 16 + b_r) * 64 + ks * 32 + b_c)));
                #pragma unroll
                for (int mi = 0; mi < 4; mi++)
                    #pragma unroll
                    for (int nj = 0; nj < 4; nj++)
                        mma_f16(acc[mi][nj], ah[mi], &bl[nj >> 1][(nj & 1) * 2]);
            }
        }

        // prefetch chunk k+NSTG-1
        const int cl = k + NSTG - 1;
        if (cl < nk) {
            uint32_t st = stage0 + (cl % NSTG) * STAGE_BYTES;
            load_tile(A_hi, row0, cl * 32, K, st + 0 * TILE_BYTES, tid);
            load_tile(A_lo, row0, cl * 32, K, st + 1 * TILE_BYTES, tid);
            load_tile(B_hi, col0, cl * 32, K, st + 2 * TILE_BYTES, tid);
            if (TERMS >= 3)
                load_tile(B_lo, col0, cl * 32, K, st + 3 * TILE_BYTES, tid);
            cp_commit();
        }
    }

    // ---- epilogue ----
    const float* bp = bias + (long long)z * DIM;   // only read when BIAS
    const bool doF32 = (EPI == 0 || EPI == 2) && !(SKIPZ0 && z == 0);
    #pragma unroll
    for (int mi = 0; mi < 4; mi++) {
        const int r0 = row0 + wm + mi * 16 + (lane >> 2);
        #pragma unroll
        for (int nj = 0; nj < 4; nj++) {
            const int c = col0 + wn + nj * 8 + (lane & 3) * 2;
            float v0 = acc[mi][nj][0], v1 = acc[mi][nj][1];
            float v2 = acc[mi][nj][2], v3 = acc[mi][nj][3];
            if (BIAS) {
                float b0 = bp[c], b1 = bp[c + 1];
                v0 += b0; v1 += b1; v2 += b0; v3 += b1;
            }
            if (doF32) {
                float* cp = Cf + (long long)z * cB + (long long)r0 * ldC + c;
                *(float2*)cp = make_float2(v0, v1);
                *(float2*)(cp + 8LL * ldC) = make_float2(v2, v3);
            }
            if (EPI >= 1) {
                __half h0, l0, h1, l1;
                split1(v0, h0, l0); split1(v1, h1, l1);
                __half* hp = Chi + (long long)z * cB + (long long)r0 * ldC + c;
                __half* lp = Clo + (long long)z * cB + (long long)r0 * ldC + c;
                *(__half2*)hp = __halves2half2(h0, h1);
                *(__half2*)lp = __halves2half2(l0, l1);
                split1(v2, h0, l0); split1(v3, h1, l1);
                *(__half2*)(hp + 8LL * ldC) = __halves2half2(h0, h1);
                *(__half2*)(lp + 8LL * ldC) = __halves2half2(l0, l1);
            }
        }
    }
}

// ---------------------------------------------------------------------------
// elementwise fp32 -> fp16 hi/lo split
// ---------------------------------------------------------------------------
__global__ void split_kernel(const float* __restrict__ in,
                             __half* __restrict__ hi,
                             __half* __restrict__ lo, int n4)
{
    int i = blockIdx.x * blockDim.x + threadIdx.x;
    if (i >= n4) return;
    float4 v = ((const float4*)in)[i];
    __half h0, l0, h1, l1, h2, l2, h3, l3;
    split1(v.x, h0, l0); split1(v.y, h1, l1);
    split1(v.z, h2, l2); split1(v.w, h3, l3);
    __half2 ha = __halves2half2(h0, h1), hb = __halves2half2(h2, h3);
    __half2 la = __halves2half2(l0, l1), lb = __halves2half2(l2, l3);
    ((uint2*)hi)[i] = make_uint2(*(uint32_t*)&ha, *(uint32_t*)&hb);
    ((uint2*)lo)[i] = make_uint2(*(uint32_t*)&la, *(uint32_t*)&lb);
}

// transpose + split: fp32 [Z][R][C] -> fp16 hi/lo [Z][C][R]
__global__ void tsplit_kernel(const float* __restrict__ in,
                              __half* __restrict__ hi,
                              __half* __restrict__ lo, int R, int C)
{
    __shared__ float t[32][33];
    const long long zoff = (long long)blockIdx.z * R * C;
    const int c0 = blockIdx.x * 32, r0 = blockIdx.y * 32;
    const int tx = threadIdx.x, ty = threadIdx.y;
    #pragma unroll
    for (int i = 0; i < 4; i++)
        t[ty + 8 * i][tx] = in[zoff + (long long)(r0 + ty + 8 * i) * C + c0 + tx];
    __syncthreads();
    #pragma unroll
    for (int i = 0; i < 4; i++) {
        float v = t[tx][ty + 8 * i];
        __half h, l; split1(v, h, l);
        long long o = zoff + (long long)(c0 + ty + 8 * i) * R + r0 + tx;
        hi[o] = h; lo[o] = l;
    }
}

// ---------------------------------------------------------------------------
// combined biases: out[j*DIM + h] = sum_e b[e] * W_j[e, h],  j in {q,k,v}
// ---------------------------------------------------------------------------
__global__ void bias_combine_kernel(const float* __restrict__ b,
                                    const float* __restrict__ Wq,
                                    const float* __restrict__ Wk,
                                    const float* __restrict__ Wv,
                                    float* __restrict__ out)
{
    const int h = blockIdx.x * 256 + threadIdx.x;
    const float* W = (blockIdx.y == 0) ? Wq : (blockIdx.y == 1) ? Wk : Wv;
    float s = 0.0f;
    #pragma unroll 8
    for (int e = 0; e < DIM; e++) s += b[e] * W[(long long)e * DIM + h];
    out[blockIdx.y * DIM + h] = s;
}

// ---------------------------------------------------------------------------
// causal softmax fp32 scores -> fp16 hi/lo probs; exp cached in registers.
// zero-fill to end of the diagonal 128-block (PV GEMM never reads beyond).
// ---------------------------------------------------------------------------
__global__ __launch_bounds__(256)
void softmax_causal_kernel(const float* __restrict__ S,
                           __half* __restrict__ Phi,
                           __half* __restrict__ Plo)
{
    const int q = blockIdx.x, b = blockIdx.y;
    const long long off = ((long long)b * SEQ + q) * SEQ;
    const float* row = S + off;
    const int n = q + 1;
    const int tid = threadIdx.x;
    __shared__ float sh[8];

    float rv[8];
    int cnt = 0;
    float m = -INFINITY;
    for (int i = tid; i < n; i += 256) {
        float v = row[i];
        rv[cnt++] = v;
        m = fmaxf(m, v);
    }
    #pragma unroll
    for (int o = 16; o; o >>= 1) m = fmaxf(m, __shfl_xor_sync(0xffffffffu, m, o));
    if ((tid & 31) == 0) sh[tid >> 5] = m;
    __syncthreads();
    float mr = sh[0];
    #pragma unroll
    for (int i = 1; i < 8; i++) mr = fmaxf(mr, sh[i]);
    __syncthreads();

    float s = 0.0f;
    #pragma unroll
    for (int j = 0; j < 8; j++)
        if (j < cnt) { rv[j] = __expf(rv[j] - mr); s += rv[j]; }
    #pragma unroll
    for (int o = 16; o; o >>= 1) s += __shfl_xor_sync(0xffffffffu, s, o);
    if ((tid & 31) == 0) sh[tid >> 5] = s;
    __syncthreads();
    float sr = 0.0f;
    #pragma unroll
    for (int i = 0; i < 8; i++) sr += sh[i];
    const float inv = 1.0f / sr;

    cnt = 0;
    for (int i = tid; i < n; i += 256) {
        float p = rv[cnt++] * inv;
        __half h, l; split1(p, h, l);
        Phi[off + i] = h; Plo[off + i] = l;
    }
    const int fend = ((q >> 7) + 1) << 7;   // end of diagonal 128-block
    const __half z16 = __float2half(0.0f);
    for (int i = n + tid; i < fend; i += 256) {
        Phi[off + i] = z16; Plo[off + i] = z16;
    }
}

// ---------------------------------------------------------------------------
extern "C" void kernel_launch(void* const* d_in, const int* in_sizes, int n_in,
                              void* d_out, int out_size)
{
    const float* x_batch = (const float*)d_in[0];
    const float* lin_w   = (const float*)d_in[1];
    const float* lin_b   = (const float*)d_in[2];
    const float* W_q     = (const float*)d_in[3];
    const float* W_k     = (const float*)d_in[4];
    const float* W_v     = (const float*)d_in[5];

    float* outF = (float*)d_out;
    float* outK = outF + (long long)BS * DIM;
    float* outV = outK + (long long)BS * DIM;

    __half *xb_hi, *xb_lo, *wT_hi, *wT_lo, *lwT_hi, *lwT_lo, *c_hi, *c_lo;
    __half *qkv_hi, *qkv_lo, *vt_hi, *vt_lo, *p_hi, *p_lo;
    float *bias3, *ss;
    cudaGetSymbolAddress((void**)&xb_hi, g_xb_hi); cudaGetSymbolAddress((void**)&xb_lo, g_xb_lo);
    cudaGetSymbolAddress((void**)&wT_hi, g_wT_hi); cudaGetSymbolAddress((void**)&wT_lo, g_wT_lo);
    cudaGetSymbolAddress((void**)&lwT_hi, g_lwT_hi); cudaGetSymbolAddress((void**)&lwT_lo, g_lwT_lo);
    cudaGetSymbolAddress((void**)&c_hi, g_c_hi);   cudaGetSymbolAddress((void**)&c_lo, g_c_lo);
    cudaGetSymbolAddress((void**)&bias3, g_bias);
    cudaGetSymbolAddress((void**)&qkv_hi, g_qkv_hi); cudaGetSymbolAddress((void**)&qkv_lo, g_qkv_lo);
    cudaGetSymbolAddress((void**)&vt_hi, g_vt_hi); cudaGetSymbolAddress((void**)&vt_lo, g_vt_lo);
    cudaGetSymbolAddress((void**)&p_hi,  g_p_hi);  cudaGetSymbolAddress((void**)&p_lo,  g_p_lo);
    cudaGetSymbolAddress((void**)&ss, g_s);

    cudaFuncSetAttribute(gemm_mma<1, false, false, false, 3, false>, cudaFuncAttributeMaxDynamicSharedMemorySize, SMEM_DYN);
    cudaFuncSetAttribute(gemm_mma<2, true,  false, false, 3, true >, cudaFuncAttributeMaxDynamicSharedMemorySize, SMEM_DYN);
    cudaFuncSetAttribute(gemm_mma<0, true,  false, false, 3, false>, cudaFuncAttributeMaxDynamicSharedMemorySize, SMEM_DYN);
    cudaFuncSetAttribute(gemm_mma<0, false, true,  false, 3, false>, cudaFuncAttributeMaxDynamicSharedMemorySize, SMEM_DYN);
    cudaFuncSetAttribute(gemm_mma<0, false, false, true,  2, false>, cudaFuncAttributeMaxDynamicSharedMemorySize, SMEM_DYN);

    const long long DD = (long long)DIM * DIM;

    // ---- lazily-created side stream + events (identical launches each call) ----
    static cudaStream_t s2 = nullptr;
    static cudaEvent_t e0 = nullptr, e2 = nullptr, e3 = nullptr, e4 = nullptr;
    static bool tried = false;
    if (!tried) {
        tried = true;
        if (cudaStreamCreateWithFlags(&s2, cudaStreamNonBlocking) != cudaSuccess) s2 = nullptr;
        if (s2) {
            cudaEventCreateWithFlags(&e0, cudaEventDisableTiming);
            cudaEventCreateWithFlags(&e2, cudaEventDisableTiming);
            cudaEventCreateWithFlags(&e3, cudaEventDisableTiming);
            cudaEventCreateWithFlags(&e4, cudaEventDisableTiming);
        }
    }
    const bool ok = (s2 != nullptr);
    cudaStream_t sb = ok ? s2 : (cudaStream_t)0;   // side-branch stream

    // ---- fork: prep chain on side stream, xb split on main ----
    if (ok) { cudaEventRecord(e0, 0); cudaStreamWaitEvent(sb, e0, 0); }
    {
        dim3 g(DIM / 32, DIM / 32, 1), t(32, 8);
        tsplit_kernel<<<g, t, 0, sb>>>(lin_w, lwT_hi, lwT_lo, DIM, DIM);
        tsplit_kernel<<<g, t, 0, sb>>>(W_q, wT_hi + 0 * DD, wT_lo + 0 * DD, DIM, DIM);
        tsplit_kernel<<<g, t, 0, sb>>>(W_k, wT_hi + 1 * DD, wT_lo + 1 * DD, DIM, DIM);
        tsplit_kernel<<<g, t, 0, sb>>>(W_v, wT_hi + 2 * DD, wT_lo + 2 * DD, DIM, DIM);
    }
    bias_combine_kernel<<<dim3(DIM / 256, 3), 256, 0, sb>>>(lin_b, W_q, W_k, W_v, bias3);
    {   // combined weights: C_j[h][d] = sum_e W_j[e][h] * lw[e][d]
        dim3 g(DIM / 128, DIM / 128, 3);
        gemm_mma<1, false, false, false, 3, false><<<g, 256, SMEM_DYN, sb>>>(
            wT_hi, wT_lo, lwT_hi, lwT_lo, nullptr,
            nullptr, c_hi, c_lo, DIM, DIM, DD, 0, DD);
    }
    if (ok) cudaEventRecord(e2, sb);

    split_kernel<<<(BS * DIM / 4 + 255) / 256, 256>>>(x_batch, xb_hi, xb_lo, BS * DIM / 4);
    if (ok) { cudaStreamWaitEvent(0, e2, 0); cudaEventRecord(e3, 0); cudaStreamWaitEvent(sb, e3, 0); }

    // ---- side branch: V = xb @ Cv^T + bv (fp32 only) -> V transpose+split ----
    {
        dim3 g(DIM / 128, BS / 128, 1);
        gemm_mma<0, true, false, false, 3, false><<<g, 256, SMEM_DYN, sb>>>(
            xb_hi, xb_lo, c_hi + 2 * DD, c_lo + 2 * DD, bias3 + 2 * DIM,
            outV, nullptr, nullptr, DIM, DIM, 0, 0, 0);
    }
    {
        dim3 g(DIM / 32, SEQ / 32, BATCH), t(32, 8);
        tsplit_kernel<<<g, t, 0, sb>>>(outV, vt_hi, vt_lo, SEQ, DIM);
    }
    if (ok) cudaEventRecord(e4, sb);

    // ---- main: Q,K = xb @ C^T + b (z in {0,1}; EPI=2, skip z=0 fp32) ----
    {
        dim3 g(DIM / 128, BS / 128, 2);
        gemm_mma<2, true, false, false, 3, true><<<g, 256, SMEM_DYN>>>(
            xb_hi, xb_lo, c_hi, c_lo, bias3,
            outF, qkv_hi, qkv_lo, DIM, DIM,
            0, DD, (long long)BS * DIM);
    }
    // ---- scores = Q @ K^T (batched, causal block skip) ----
    {
        const __half* q_hi = qkv_hi;                       const __half* q_lo = qkv_lo;
        const __half* k_hi = qkv_hi + (long long)BS * DIM; const __half* k_lo = qkv_lo + (long long)BS * DIM;
        dim3 g(SEQ / 128, SEQ / 128, BATCH);
        gemm_mma<0, false, true, false, 3, false><<<g, 256, SMEM_DYN>>>(
            q_hi, q_lo, k_hi, k_lo, nullptr,
            ss, nullptr, nullptr, DIM, SEQ,
            (long long)SEQ * DIM, (long long)SEQ * DIM, (long long)SEQ * SEQ);
    }
    // ---- softmax -> fp16 split probs ----
    {
        dim3 g(SEQ, BATCH);
        softmax_causal_kernel<<<g, 256>>>(ss, p_hi, p_lo);
    }
    // ---- join V branch, then F = P @ Vt (batched, causal K-limit, 2-term) ----
    if (ok) cudaStreamWaitEvent(0, e4, 0);
    {
        dim3 g(DIM / 128, SEQ / 128, BATCH);
        gemm_mma<0, false, false, true, 2, false><<<g, 256, SMEM_DYN>>>(
            p_hi, p_lo, vt_hi, vt_lo, nullptr,
            outF, nullptr, nullptr, SEQ, DIM,
            (long long)SEQ * SEQ, (long long)DIM * SEQ, (long long)SEQ * DIM);
    }
}

// round 9
// speedup vs baseline: 3.9866x; 1.0165x over previous
#include <cuda_runtime.h>
#include <cuda_fp16.h>
#include <math.h>
#include <stdint.h>

#define BATCH 8
#define SEQ   2048
#define DIM   1024
#define BS    (BATCH * SEQ)   // 16384
#define HB    (BATCH / 2)     // 4 batches per half
#define HROWS (HB * SEQ)      // 8192 rows per half

// ---------------------------------------------------------------------------
// Scratch (__device__ globals: allocation-free rule)
// ---------------------------------------------------------------------------
__device__ __half g_xb_hi[BS * DIM], g_xb_lo[BS * DIM];
__device__ __half g_wT_hi[3 * DIM * DIM], g_wT_lo[3 * DIM * DIM];   // WqT,WkT,WvT [h][e]
__device__ __half g_lwT_hi[DIM * DIM], g_lwT_lo[DIM * DIM];          // lwT [d][e]
__device__ __half g_c_hi[3 * DIM * DIM], g_c_lo[3 * DIM * DIM];      // combined W' [h][d]
__device__ float  g_bias[3 * DIM];                                   // bq,bk,bv
__device__ __half g_qkv_hi[2LL * BS * DIM], g_qkv_lo[2LL * BS * DIM];// Q,K splits
__device__ __half g_vt_hi[(long long)BATCH * DIM * SEQ], g_vt_lo[(long long)BATCH * DIM * SEQ];
__device__ __half g_p_hi [(long long)BATCH * SEQ * SEQ], g_p_lo [(long long)BATCH * SEQ * SEQ];
__device__ float  g_s[(long long)BATCH * SEQ * SEQ];

// ---------------------------------------------------------------------------
// helpers
// ---------------------------------------------------------------------------
__device__ __forceinline__ uint32_t smem_u32(const void* p) {
    uint32_t a;
    asm("{ .reg .u64 t; cvta.to.shared.u64 t, %1; cvt.u32.u64 %0, t; }"
        : "=r"(a) : "l"(p));
    return a;
}

__device__ __forceinline__ void cp16(uint32_t saddr, const void* gaddr) {
    asm volatile("cp.async.cg.shared.global [%0], [%1], 16;" :: "r"(saddr), "l"(gaddr));
}
__device__ __forceinline__ void cp_commit() {
    asm volatile("cp.async.commit_group;" ::: "memory");
}
template<int N>
__device__ __forceinline__ void cp_wait_c() {
    asm volatile("cp.async.wait_group %0;" :: "n"(N) : "memory");
}

__device__ __forceinline__ void ldsm4(uint32_t (&r)[4], uint32_t addr) {
    asm volatile("ldmatrix.sync.aligned.m8n8.x4.shared.b16 {%0,%1,%2,%3}, [%4];"
        : "=r"(r[0]), "=r"(r[1]), "=r"(r[2]), "=r"(r[3]) : "r"(addr));
}

__device__ __forceinline__ void mma_f16(float* c, const uint32_t* a, const uint32_t* b) {
    asm volatile("mma.sync.aligned.m16n8k16.row.col.f32.f16.f16.f32 "
        "{%0,%1,%2,%3}, {%4,%5,%6,%7}, {%8,%9}, {%0,%1,%2,%3};"
        : "+f"(c[0]), "+f"(c[1]), "+f"(c[2]), "+f"(c[3])
        : "r"(a[0]), "r"(a[1]), "r"(a[2]), "r"(a[3]), "r"(b[0]), "r"(b[1]));
}

// SW64 swizzle for 64B rows — conflict-free ldmatrix
__device__ __forceinline__ uint32_t sw64(uint32_t off) {
    return off ^ ((off >> 3) & 0x30);
}

__device__ __forceinline__ void split1(float v, __half& h, __half& l) {
    h = __float2half(v);
    l = __float2half(v - __half2float(h));
}

// ---------------------------------------------------------------------------
// split-fp16 GEMM on HMMA: C[M,N](fp32) = (Ahi+Alo)[M,K] * (Bhi+Blo)[N,K]^T
// TERMS=3: Ah*Bh + Al*Bh + Ah*Bl ;  TERMS=2: Ah*Bh + Al*Bh
// 128x128 CTA tile, BK=32, 3-stage cp.async, 256 threads, 2 CTAs/SM (96KB).
// ONE barrier per k-chunk.
// EPI: 0 = fp32 out, 1 = fp16 hi/lo split out, 2 = both
// SKIPZ0: suppress fp32 store for z==0
// ---------------------------------------------------------------------------
#define NSTG 3
#define TILE_BYTES  8192                  // 128 rows x 64B (32 halves)
#define STAGE_BYTES (4 * TILE_BYTES)      // Ahi, Alo, Bhi, Blo  = 32KB
#define SMEM_DYN    (NSTG * STAGE_BYTES + 1024)   // 99328

// load one 128x32 fp16 tile, SW64-swizzled (2 cp.async per thread)
__device__ __forceinline__ void load_tile(const __half* __restrict__ g,
                                          int row0, int k0, int ld,
                                          uint32_t sdst, int tid) {
    #pragma unroll
    for (int i = 0; i < 2; i++) {
        int gr = i * 256 + tid;          // 0..511
        int r  = gr >> 2;                // tile row 0..127
        int sec = gr & 3;                // 16B sector 0..3
        cp16(sdst + sw64((uint32_t)(r * 64 + sec * 16)),
             (const void*)(g + (long long)(row0 + r) * ld + (k0 + sec * 8)));
    }
}

template<int EPI, bool BIAS, bool CAUSAL, bool KLIM, int TERMS, bool SKIPZ0>
__global__ void __launch_bounds__(256, 2)
gemm_mma(const __half* __restrict__ Ahi, const __half* __restrict__ Alo,
         const __half* __restrict__ Bhi, const __half* __restrict__ Blo,
         const float* __restrict__ bias,
         float* __restrict__ Cf, __half* __restrict__ Chi, __half* __restrict__ Clo,
         int K, int ldC,
         long long aB, long long bB, long long cB)
{
    const int bx = blockIdx.x, z = blockIdx.z;
    int by = blockIdx.y;
    if (CAUSAL && bx > by) return;
    if (KLIM) by = gridDim.y - 1 - by;    // longest tiles first

    extern __shared__ char smem[];
    const uint32_t stage0 = (smem_u32(smem) + 1023u) & ~1023u;

    const int tid  = threadIdx.x;
    const int lane = tid & 31;
    const int wid  = tid >> 5;
    const int wm   = (wid & 1) * 64;     // warp m offset in tile
    const int wn   = (wid >> 1) * 32;    // warp n offset in tile

    const __half* A_hi = Ahi + (long long)z * aB;
    const __half* A_lo = Alo + (long long)z * aB;
    const __half* B_hi = Bhi + (long long)z * bB;
    const __half* B_lo = Blo + (long long)z * bB;

    int nk = K >> 5;
    if (KLIM) { int lim = 4 * (by + 1); if (lim < nk) nk = lim; }
    const int row0 = by * 128;
    const int col0 = bx * 128;

    float acc[4][4][4];
    #pragma unroll
    for (int i = 0; i < 4; i++)
        #pragma unroll
        for (int j = 0; j < 4; j++)
            #pragma unroll
            for (int c = 0; c < 4; c++) acc[i][j][c] = 0.0f;

    // per-lane ldmatrix address components
    const int a_r = ((lane >> 3) & 1) * 8 + (lane & 7);   // + mi*16 + wm
    const int a_c = (lane >> 4) * 16;                      // + ks*32
    const int b_r = ((lane >> 4) & 1) * 8 + (lane & 7);    // + pair*16 + wn
    const int b_c = ((lane >> 3) & 1) * 16;                // + ks*32

    // prologue: NSTG-1 chunks in flight (nk >= 4 always here)
    #pragma unroll
    for (int c = 0; c < NSTG - 1; c++) {
        uint32_t st = stage0 + c * STAGE_BYTES;
        load_tile(A_hi, row0, c * 32, K, st + 0 * TILE_BYTES, tid);
        load_tile(A_lo, row0, c * 32, K, st + 1 * TILE_BYTES, tid);
        load_tile(B_hi, col0, c * 32, K, st + 2 * TILE_BYTES, tid);
        if (TERMS >= 3)
            load_tile(B_lo, col0, c * 32, K, st + 3 * TILE_BYTES, tid);
        cp_commit();
    }

    for (int k = 0; k < nk; k++) {
        const int s = k % NSTG;
        if (k < nk - 1) cp_wait_c<NSTG - 2>(); else cp_wait_c<0>();
        __syncthreads();

        const uint32_t sAh = stage0 + s * STAGE_BYTES + 0 * TILE_BYTES;
        const uint32_t sAl = sAh + TILE_BYTES;
        const uint32_t sBh = sAh + 2 * TILE_BYTES;
        const uint32_t sBl = sAh + 3 * TILE_BYTES;

        #pragma unroll
        for (int ks = 0; ks < 2; ks++) {
            uint32_t ah[4][4], bh[2][4];
            #pragma unroll
            for (int mi = 0; mi < 4; mi++)
                ldsm4(ah[mi], sAh + sw64((uint32_t)((wm + mi * 16 + a_r) * 64 + ks * 32 + a_c)));
            #pragma unroll
            for (int p = 0; p < 2; p++)
                ldsm4(bh[p], sBh + sw64((uint32_t)((wn + p * 16 + b_r) * 64 + ks * 32 + b_c)));
            // term 1: Ah*Bh
            #pragma unroll
            for (int mi = 0; mi < 4; mi++)
                #pragma unroll
                for (int nj = 0; nj < 4; nj++)
                    mma_f16(acc[mi][nj], ah[mi], &bh[nj >> 1][(nj & 1) * 2]);
            // term 2: Al*Bh
            {
                uint32_t al[4][4];
                #pragma unroll
                for (int mi = 0; mi < 4; mi++)
                    ldsm4(al[mi], sAl + sw64((uint32_t)((wm + mi * 16 + a_r) * 64 + ks * 32 + a_c)));
                #pragma unroll
                for (int mi = 0; mi < 4; mi++)
                    #pragma unroll
                    for (int nj = 0; nj < 4; nj++)
                        mma_f16(acc[mi][nj], al[mi], &bh[nj >> 1][(nj & 1) * 2]);
            }
            // term 3: Ah*Bl
            if (TERMS >= 3) {
                uint32_t bl[2][4];
                #pragma unroll
                for (int p = 0; p < 2; p++)
                    ldsm4(bl[p], sBl + sw64((uint32_t)((wn + p * 16 + b_r) * 64 + ks * 32 + b_c)));
                #pragma unroll
                for (int mi = 0; mi < 4; mi++)
                    #pragma unroll
                    for (int nj = 0; nj < 4; nj++)
                        mma_f16(acc[mi][nj], ah[mi], &bl[nj >> 1][(nj & 1) * 2]);
            }
        }

        // prefetch chunk k+NSTG-1
        const int cl = k + NSTG - 1;
        if (cl < nk) {
            uint32_t st = stage0 + (cl % NSTG) * STAGE_BYTES;
            load_tile(A_hi, row0, cl * 32, K, st + 0 * TILE_BYTES, tid);
            load_tile(A_lo, row0, cl * 32, K, st + 1 * TILE_BYTES, tid);
            load_tile(B_hi, col0, cl * 32, K, st + 2 * TILE_BYTES, tid);
            if (TERMS >= 3)
                load_tile(B_lo, col0, cl * 32, K, st + 3 * TILE_BYTES, tid);
            cp_commit();
        }
    }

    // ---- epilogue ----
    const float* bp = bias + (long long)z * DIM;   // only read when BIAS
    const bool doF32 = (EPI == 0 || EPI == 2) && !(SKIPZ0 && z == 0);
    #pragma unroll
    for (int mi = 0; mi < 4; mi++) {
        const int r0 = row0 + wm + mi * 16 + (lane >> 2);
        #pragma unroll
        for (int nj = 0; nj < 4; nj++) {
            const int c = col0 + wn + nj * 8 + (lane & 3) * 2;
            float v0 = acc[mi][nj][0], v1 = acc[mi][nj][1];
            float v2 = acc[mi][nj][2], v3 = acc[mi][nj][3];
            if (BIAS) {
                float b0 = bp[c], b1 = bp[c + 1];
                v0 += b0; v1 += b1; v2 += b0; v3 += b1;
            }
            if (doF32) {
                float* cp = Cf + (long long)z * cB + (long long)r0 * ldC + c;
                *(float2*)cp = make_float2(v0, v1);
                *(float2*)(cp + 8LL * ldC) = make_float2(v2, v3);
            }
            if (EPI >= 1) {
                __half h0, l0, h1, l1;
                split1(v0, h0, l0); split1(v1, h1, l1);
                __half* hp = Chi + (long long)z * cB + (long long)r0 * ldC + c;
                __half* lp = Clo + (long long)z * cB + (long long)r0 * ldC + c;
                *(__half2*)hp = __halves2half2(h0, h1);
                *(__half2*)lp = __halves2half2(l0, l1);
                split1(v2, h0, l0); split1(v3, h1, l1);
                *(__half2*)(hp + 8LL * ldC) = __halves2half2(h0, h1);
                *(__half2*)(lp + 8LL * ldC) = __halves2half2(l0, l1);
            }
        }
    }
}

// ---------------------------------------------------------------------------
// elementwise fp32 -> fp16 hi/lo split
// ---------------------------------------------------------------------------
__global__ void split_kernel(const float* __restrict__ in,
                             __half* __restrict__ hi,
                             __half* __restrict__ lo, int n4)
{
    int i = blockIdx.x * blockDim.x + threadIdx.x;
    if (i >= n4) return;
    float4 v = ((const float4*)in)[i];
    __half h0, l0, h1, l1, h2, l2, h3, l3;
    split1(v.x, h0, l0); split1(v.y, h1, l1);
    split1(v.z, h2, l2); split1(v.w, h3, l3);
    __half2 ha = __halves2half2(h0, h1), hb = __halves2half2(h2, h3);
    __half2 la = __halves2half2(l0, l1), lb = __halves2half2(l2, l3);
    ((uint2*)hi)[i] = make_uint2(*(uint32_t*)&ha, *(uint32_t*)&hb);
    ((uint2*)lo)[i] = make_uint2(*(uint32_t*)&la, *(uint32_t*)&lb);
}

// transpose + split: fp32 [Z][R][C] -> fp16 hi/lo [Z][C][R]
__global__ void tsplit_kernel(const float* __restrict__ in,
                              __half* __restrict__ hi,
                              __half* __restrict__ lo, int R, int C)
{
    __shared__ float t[32][33];
    const long long zoff = (long long)blockIdx.z * R * C;
    const int c0 = blockIdx.x * 32, r0 = blockIdx.y * 32;
    const int tx = threadIdx.x, ty = threadIdx.y;
    #pragma unroll
    for (int i = 0; i < 4; i++)
        t[ty + 8 * i][tx] = in[zoff + (long long)(r0 + ty + 8 * i) * C + c0 + tx];
    __syncthreads();
    #pragma unroll
    for (int i = 0; i < 4; i++) {
        float v = t[tx][ty + 8 * i];
        __half h, l; split1(v, h, l);
        long long o = zoff + (long long)(c0 + ty + 8 * i) * R + r0 + tx;
        hi[o] = h; lo[o] = l;
    }
}

// ---------------------------------------------------------------------------
// combined biases: out[j*DIM + h] = sum_e b[e] * W_j[e, h],  j in {q,k,v}
// ---------------------------------------------------------------------------
__global__ void bias_combine_kernel(const float* __restrict__ b,
                                    const float* __restrict__ Wq,
                                    const float* __restrict__ Wk,
                                    const float* __restrict__ Wv,
                                    float* __restrict__ out)
{
    const int h = blockIdx.x * 256 + threadIdx.x;
    const float* W = (blockIdx.y == 0) ? Wq : (blockIdx.y == 1) ? Wk : Wv;
    float s = 0.0f;
    #pragma unroll 8
    for (int e = 0; e < DIM; e++) s += b[e] * W[(long long)e * DIM + h];
    out[blockIdx.y * DIM + h] = s;
}

// ---------------------------------------------------------------------------
// causal softmax fp32 scores -> fp16 hi/lo probs; exp cached in registers.
// zero-fill to end of the diagonal 128-block (PV GEMM never reads beyond).
// ---------------------------------------------------------------------------
__global__ __launch_bounds__(256)
void softmax_causal_kernel(const float* __restrict__ S,
                           __half* __restrict__ Phi,
                           __half* __restrict__ Plo)
{
    const int q = blockIdx.x, b = blockIdx.y;
    const long long off = ((long long)b * SEQ + q) * SEQ;
    const float* row = S + off;
    const int n = q + 1;
    const int tid = threadIdx.x;
    __shared__ float sh[8];

    float rv[8];
    int cnt = 0;
    float m = -INFINITY;
    for (int i = tid; i < n; i += 256) {
        float v = row[i];
        rv[cnt++] = v;
        m = fmaxf(m, v);
    }
    #pragma unroll
    for (int o = 16; o; o >>= 1) m = fmaxf(m, __shfl_xor_sync(0xffffffffu, m, o));
    if ((tid & 31) == 0) sh[tid >> 5] = m;
    __syncthreads();
    float mr = sh[0];
    #pragma unroll
    for (int i = 1; i < 8; i++) mr = fmaxf(mr, sh[i]);
    __syncthreads();

    float s = 0.0f;
    #pragma unroll
    for (int j = 0; j < 8; j++)
        if (j < cnt) { rv[j] = __expf(rv[j] - mr); s += rv[j]; }
    #pragma unroll
    for (int o = 16; o; o >>= 1) s += __shfl_xor_sync(0xffffffffu, s, o);
    if ((tid & 31) == 0) sh[tid >> 5] = s;
    __syncthreads();
    float sr = 0.0f;
    #pragma unroll
    for (int i = 0; i < 8; i++) sr += sh[i];
    const float inv = 1.0f / sr;

    cnt = 0;
    for (int i = tid; i < n; i += 256) {
        float p = rv[cnt++] * inv;
        __half h, l; split1(p, h, l);
        Phi[off + i] = h; Plo[off + i] = l;
    }
    const int fend = ((q >> 7) + 1) << 7;   // end of diagonal 128-block
    const __half z16 = __float2half(0.0f);
    for (int i = n + tid; i < fend; i += 256) {
        Phi[off + i] = z16; Plo[off + i] = z16;
    }
}

// ---------------------------------------------------------------------------
extern "C" void kernel_launch(void* const* d_in, const int* in_sizes, int n_in,
                              void* d_out, int out_size)
{
    const float* x_batch = (const float*)d_in[0];
    const float* lin_w   = (const float*)d_in[1];
    const float* lin_b   = (const float*)d_in[2];
    const float* W_q     = (const float*)d_in[3];
    const float* W_k     = (const float*)d_in[4];
    const float* W_v     = (const float*)d_in[5];

    float* outF = (float*)d_out;
    float* outK = outF + (long long)BS * DIM;
    float* outV = outK + (long long)BS * DIM;

    __half *xb_hi, *xb_lo, *wT_hi, *wT_lo, *lwT_hi, *lwT_lo, *c_hi, *c_lo;
    __half *qkv_hi, *qkv_lo, *vt_hi, *vt_lo, *p_hi, *p_lo;
    float *bias3, *ss;
    cudaGetSymbolAddress((void**)&xb_hi, g_xb_hi); cudaGetSymbolAddress((void**)&xb_lo, g_xb_lo);
    cudaGetSymbolAddress((void**)&wT_hi, g_wT_hi); cudaGetSymbolAddress((void**)&wT_lo, g_wT_lo);
    cudaGetSymbolAddress((void**)&lwT_hi, g_lwT_hi); cudaGetSymbolAddress((void**)&lwT_lo, g_lwT_lo);
    cudaGetSymbolAddress((void**)&c_hi, g_c_hi);   cudaGetSymbolAddress((void**)&c_lo, g_c_lo);
    cudaGetSymbolAddress((void**)&bias3, g_bias);
    cudaGetSymbolAddress((void**)&qkv_hi, g_qkv_hi); cudaGetSymbolAddress((void**)&qkv_lo, g_qkv_lo);
    cudaGetSymbolAddress((void**)&vt_hi, g_vt_hi); cudaGetSymbolAddress((void**)&vt_lo, g_vt_lo);
    cudaGetSymbolAddress((void**)&p_hi,  g_p_hi);  cudaGetSymbolAddress((void**)&p_lo,  g_p_lo);
    cudaGetSymbolAddress((void**)&ss, g_s);

    cudaFuncSetAttribute(gemm_mma<1, false, false, false, 3, false>, cudaFuncAttributeMaxDynamicSharedMemorySize, SMEM_DYN);
    cudaFuncSetAttribute(gemm_mma<2, true,  false, false, 3, true >, cudaFuncAttributeMaxDynamicSharedMemorySize, SMEM_DYN);
    cudaFuncSetAttribute(gemm_mma<0, true,  false, false, 3, false>, cudaFuncAttributeMaxDynamicSharedMemorySize, SMEM_DYN);
    cudaFuncSetAttribute(gemm_mma<0, false, true,  false, 3, false>, cudaFuncAttributeMaxDynamicSharedMemorySize, SMEM_DYN);
    cudaFuncSetAttribute(gemm_mma<0, false, false, true,  2, false>, cudaFuncAttributeMaxDynamicSharedMemorySize, SMEM_DYN);

    const long long DD   = (long long)DIM * DIM;
    const long long HOFF = (long long)HROWS * DIM;        // row offset per half
    const long long SOFF = (long long)HB * SEQ * SEQ;     // score offset per half
    const long long VOFF = (long long)HB * DIM * SEQ;     // vt offset per half

    // ---- lazily-created side stream + events ----
    static cudaStream_t s2 = nullptr;
    static cudaEvent_t e0 = nullptr, e2 = nullptr, e3 = nullptr, eV = nullptr, eE = nullptr;
    static bool tried = false;
    if (!tried) {
        tried = true;
        if (cudaStreamCreateWithFlags(&s2, cudaStreamNonBlocking) != cudaSuccess) s2 = nullptr;
        if (s2) {
            cudaEventCreateWithFlags(&e0, cudaEventDisableTiming);
            cudaEventCreateWithFlags(&e2, cudaEventDisableTiming);
            cudaEventCreateWithFlags(&e3, cudaEventDisableTiming);
            cudaEventCreateWithFlags(&eV, cudaEventDisableTiming);
            cudaEventCreateWithFlags(&eE, cudaEventDisableTiming);
        }
    }
    const bool ok = (s2 != nullptr);
    cudaStream_t sb = ok ? s2 : (cudaStream_t)0;

    // ================= fork: prep on side, xb split on main =================
    if (ok) { cudaEventRecord(e0, 0); cudaStreamWaitEvent(sb, e0, 0); }
    {
        dim3 g(DIM / 32, DIM / 32, 1), t(32, 8);
        tsplit_kernel<<<g, t, 0, sb>>>(lin_w, lwT_hi, lwT_lo, DIM, DIM);
        tsplit_kernel<<<g, t, 0, sb>>>(W_q, wT_hi + 0 * DD, wT_lo + 0 * DD, DIM, DIM);
        tsplit_kernel<<<g, t, 0, sb>>>(W_k, wT_hi + 1 * DD, wT_lo + 1 * DD, DIM, DIM);
        tsplit_kernel<<<g, t, 0, sb>>>(W_v, wT_hi + 2 * DD, wT_lo + 2 * DD, DIM, DIM);
    }
    bias_combine_kernel<<<dim3(DIM / 256, 3), 256, 0, sb>>>(lin_b, W_q, W_k, W_v, bias3);
    {   // combined weights: C_j[h][d] = sum_e W_j[e][h] * lw[e][d]
        dim3 g(DIM / 128, DIM / 128, 3);
        gemm_mma<1, false, false, false, 3, false><<<g, 256, SMEM_DYN, sb>>>(
            wT_hi, wT_lo, lwT_hi, lwT_lo, nullptr,
            nullptr, c_hi, c_lo, DIM, DIM, DD, 0, DD);
    }
    if (ok) cudaEventRecord(e2, sb);

    split_kernel<<<(BS * DIM / 4 + 255) / 256, 256>>>(x_batch, xb_hi, xb_lo, BS * DIM / 4);
    if (ok) { cudaStreamWaitEvent(0, e2, 0); cudaEventRecord(e3, 0); cudaStreamWaitEvent(sb, e3, 0); }

    // ====== side pipeline (half 1, b4..7): QKV -> scores -> softmax =========
    {
        dim3 g(DIM / 128, HROWS / 128, 2);
        gemm_mma<2, true, false, false, 3, true><<<g, 256, SMEM_DYN, sb>>>(
            xb_hi + HOFF, xb_lo + HOFF, c_hi, c_lo, bias3,
            outF + HOFF, qkv_hi + HOFF, qkv_lo + HOFF, DIM, DIM,
            0, DD, (long long)BS * DIM);
    }
    {
        dim3 g(SEQ / 128, SEQ / 128, HB);
        gemm_mma<0, false, true, false, 3, false><<<g, 256, SMEM_DYN, sb>>>(
            qkv_hi + HOFF, qkv_lo + HOFF,
            qkv_hi + (long long)BS * DIM + HOFF, qkv_lo + (long long)BS * DIM + HOFF,
            nullptr, ss + SOFF, nullptr, nullptr, DIM, SEQ,
            (long long)SEQ * DIM, (long long)SEQ * DIM, (long long)SEQ * SEQ);
    }
    {
        dim3 g(SEQ, HB);
        softmax_causal_kernel<<<g, 256, 0, sb>>>(ss + SOFF, p_hi + SOFF, p_lo + SOFF);
    }

    // ====== main: V chain (records eV BEFORE side waits on it) ==============
    {   // V = xb @ Cv^T + bv (fp32 only, all batches)
        dim3 g(DIM / 128, BS / 128, 1);
        gemm_mma<0, true, false, false, 3, false><<<g, 256, SMEM_DYN>>>(
            xb_hi, xb_lo, c_hi + 2 * DD, c_lo + 2 * DD, bias3 + 2 * DIM,
            outV, nullptr, nullptr, DIM, DIM, 0, 0, 0);
    }
    {   // V transpose+split (all batches)
        dim3 g(DIM / 32, SEQ / 32, BATCH), t(32, 8);
        tsplit_kernel<<<g, t>>>(outV, vt_hi, vt_lo, SEQ, DIM);
    }
    if (ok) cudaEventRecord(eV, 0);

    // ====== side: PV half 1 (waits eV — recorded above in issue order) ======
    if (ok) cudaStreamWaitEvent(sb, eV, 0);
    {
        dim3 g(DIM / 128, SEQ / 128, HB);
        gemm_mma<0, false, false, true, 2, false><<<g, 256, SMEM_DYN, sb>>>(
            p_hi + SOFF, p_lo + SOFF, vt_hi + VOFF, vt_lo + VOFF, nullptr,
            outF + HOFF, nullptr, nullptr, SEQ, DIM,
            (long long)SEQ * SEQ, (long long)DIM * SEQ, (long long)SEQ * DIM);
    }
    if (ok) cudaEventRecord(eE, sb);

    // ====== main pipeline (half 0, b0..3) ====================================
    {
        dim3 g(DIM / 128, HROWS / 128, 2);
        gemm_mma<2, true, false, false, 3, true><<<g, 256, SMEM_DYN>>>(
            xb_hi, xb_lo, c_hi, c_lo, bias3,
            outF, qkv_hi, qkv_lo, DIM, DIM,
            0, DD, (long long)BS * DIM);
    }
    {
        dim3 g(SEQ / 128, SEQ / 128, HB);
        gemm_mma<0, false, true, false, 3, false><<<g, 256, SMEM_DYN>>>(
            qkv_hi, qkv_lo,
            qkv_hi + (long long)BS * DIM, qkv_lo + (long long)BS * DIM,
            nullptr, ss, nullptr, nullptr, DIM, SEQ,
            (long long)SEQ * DIM, (long long)SEQ * DIM, (long long)SEQ * SEQ);
    }
    {
        dim3 g(SEQ, HB);
        softmax_causal_kernel<<<g, 256>>>(ss, p_hi, p_lo);
    }
    {
        dim3 g(DIM / 128, SEQ / 128, HB);
        gemm_mma<0, false, false, true, 2, false><<<g, 256, SMEM_DYN>>>(
            p_hi, p_lo, vt_hi, vt_lo, nullptr,
            outF, nullptr, nullptr, SEQ, DIM,
            (long long)SEQ * SEQ, (long long)DIM * SEQ, (long long)SEQ * DIM);
    }
    // join side pipeline back into stream 0
    if (ok) cudaStreamWaitEvent(0, eE, 0);
}